// round 1
// baseline (speedup 1.0000x reference)
#include <cuda_runtime.h>

#define Bd 128
#define Sd 2048
#define Hd 256
#define Ed 256
#define VSZ 32000

// ---------------- scratch (device globals; no allocation) ----------------
__device__ float g_w2h[Bd * Hd];
__device__ float g_scores[Bd * Sd];
__device__ float g_Xa[Bd * Hd];
__device__ float g_res[Bd * Hd];
__device__ float g_h0[Bd * Hd];
__device__ float g_h1[Bd * Hd];
__device__ float g_h1T[Hd * Bd];

typedef unsigned long long u64;

__device__ __forceinline__ u64 pack2(float x, float y) {
    u64 d;
    asm("mov.b64 %0, {%1, %2};" : "=l"(d)
        : "r"(__float_as_uint(x)), "r"(__float_as_uint(y)));
    return d;
}
__device__ __forceinline__ u64 ffma2(u64 a, u64 b, u64 c) {
    u64 d;
    asm("fma.rn.f32x2 %0, %1, %2, %3;" : "=l"(d) : "l"(a), "l"(b), "l"(c));
    return d;
}
__device__ __forceinline__ float2 unpack2(u64 v) {
    unsigned lo, hi;
    asm("mov.b64 {%0, %1}, %2;" : "=r"(lo), "=r"(hi) : "l"(v));
    float2 r;
    r.x = __uint_as_float(lo);
    r.y = __uint_as_float(hi);
    return r;
}
__device__ __forceinline__ float fast_tanh(float x) {
    float y;
    asm("tanh.approx.f32 %0, %1;" : "=f"(y) : "f"(x));
    return y;
}

// ---------------- K1: w2h = hidden[1] @ W2 + b2 ----------------
__global__ void w2h_kernel(const float* __restrict__ hidden,
                           const float* __restrict__ W2,
                           const float* __restrict__ b2) {
    int b = blockIdx.x;
    int k = threadIdx.x;
    __shared__ float sh[Hd];
    sh[k] = hidden[(Bd + b) * Hd + k];  // hidden[-1] = layer 1
    __syncthreads();
    float acc = b2[k];
#pragma unroll 8
    for (int h = 0; h < Hd; h++) acc += sh[h] * W2[h * Hd + k];
    g_w2h[b * Hd + k] = acc;
}

// ---------------- K2: scores[b,s] = V . tanh(enc[b,s]@W1 + w2h[b]) --------
// GEMM M=B*S, N=256, K=256 with fused tanh+dot-V epilogue (u never stored).
// Block: 64 rows of s for one b, all 256 output cols. 256 threads (16x16).
// Thread tile: 4 rows x 16 cols (as 8 float2). FFMA2 throughout.
__global__ __launch_bounds__(256, 2)
void scores_kernel(const float* __restrict__ enc,
                   const float* __restrict__ W1,
                   const float* __restrict__ V) {
    __shared__ float enc_s[64 * 36];   // pad 36 -> conflict-free, f4-aligned
    __shared__ float w1_s[32 * 256];
    const int b = blockIdx.y;
    const int s0 = blockIdx.x * 64;
    const int tid = threadIdx.x;
    const int tx = tid & 15;
    const int ty = tid >> 4;

    u64 acc[4][8];
#pragma unroll
    for (int i = 0; i < 4; i++)
#pragma unroll
        for (int j = 0; j < 8; j++) acc[i][j] = 0ull;

    const float* encb = enc + ((size_t)b * Sd + s0) * Hd;

    for (int kk = 0; kk < Hd; kk += 32) {
        // enc tile: 64 rows x 32 k (coalesced float4)
        {
            int row = tid >> 3;
            int k4 = (tid & 7) * 4;
            float4 v0 = *(const float4*)(encb + (size_t)row * Hd + kk + k4);
            float4 v1 = *(const float4*)(encb + (size_t)(row + 32) * Hd + kk + k4);
            *(float4*)&enc_s[row * 36 + k4] = v0;
            *(float4*)&enc_s[(row + 32) * 36 + k4] = v1;
        }
        // W1 tile: 32 k x 256 cols (coalesced float4)
#pragma unroll
        for (int t = 0; t < 8; t++) {
            int q = tid + t * 256;         // float4 index, 2048 total
            int row = q >> 6;
            int c4 = (q & 63) * 4;
            *(float4*)&w1_s[row * 256 + c4] =
                *(const float4*)(W1 + (size_t)(kk + row) * Hd + c4);
        }
        __syncthreads();
#pragma unroll 4
        for (int k = 0; k < 32; k++) {
            u64 av[4];
#pragma unroll
            for (int i = 0; i < 4; i++) {
                float a = enc_s[(ty * 4 + i) * 36 + k];
                av[i] = pack2(a, a);
            }
#pragma unroll
            for (int j = 0; j < 8; j++) {
                u64 bv = *(const u64*)&w1_s[k * 256 + tx * 2 + j * 32];
#pragma unroll
                for (int i = 0; i < 4; i++) acc[i][j] = ffma2(av[i], bv, acc[i][j]);
            }
        }
        __syncthreads();
    }

    // epilogue: p[row] = sum_c V[c]*tanh(acc + w2h[b][c]); reduce over tx
    const float* w2 = g_w2h + b * Hd;
    float p[4] = {0.f, 0.f, 0.f, 0.f};
#pragma unroll
    for (int j = 0; j < 8; j++) {
        int c = tx * 2 + j * 32;
        float w2lo = w2[c], w2hi = w2[c + 1];
        float vlo = V[c], vhi = V[c + 1];
#pragma unroll
        for (int i = 0; i < 4; i++) {
            float2 a = unpack2(acc[i][j]);
            p[i] += vlo * fast_tanh(a.x + w2lo) + vhi * fast_tanh(a.y + w2hi);
        }
    }
#pragma unroll
    for (int i = 0; i < 4; i++) {
        float v = p[i];
#pragma unroll
        for (int d = 8; d >= 1; d >>= 1)
            v += __shfl_xor_sync(0xffffffffu, v, d, 16);
        if (tx == 0) g_scores[b * Sd + s0 + ty * 4 + i] = v;
    }
}

// ---------------- K3: softmax over S + Xa = a . enc ----------------
__global__ void attn_kernel(const float* __restrict__ enc) {
    const int b = blockIdx.x;
    const int tid = threadIdx.x;  // 256
    __shared__ float sa[Sd];
    __shared__ float red[256];

    float m = -1e30f;
    for (int s = tid; s < Sd; s += 256) {
        float v = g_scores[b * Sd + s];
        sa[s] = v;
        m = fmaxf(m, v);
    }
    red[tid] = m;
    __syncthreads();
    for (int d = 128; d > 0; d >>= 1) {
        if (tid < d) red[tid] = fmaxf(red[tid], red[tid + d]);
        __syncthreads();
    }
    m = red[0];
    __syncthreads();

    float sum = 0.f;
    for (int s = tid; s < Sd; s += 256) {
        float e = expf(sa[s] - m);
        sa[s] = e;
        sum += e;
    }
    red[tid] = sum;
    __syncthreads();
    for (int d = 128; d > 0; d >>= 1) {
        if (tid < d) red[tid] += red[tid + d];
        __syncthreads();
    }
    float inv = 1.f / red[0];

    // Xa[b][h]: thread owns one h (coalesced enc reads)
    int h = tid;
    const float* eb = enc + (size_t)b * Sd * Hd + h;
    float acc = 0.f;
#pragma unroll 8
    for (int s = 0; s < Sd; s++) acc += sa[s] * eb[(size_t)s * Hd];
    g_Xa[b * Hd + h] = acc * inv;
}

// ---------------- K4: res = [emb[inp]; Xa] @ W3 + b3 ----------------
__global__ void res_kernel(const int* __restrict__ inp,
                           const float* __restrict__ emb,
                           const float* __restrict__ W3,
                           const float* __restrict__ b3) {
    const int b = blockIdx.x;
    const int k = threadIdx.x;
    __shared__ float cat[Ed + Hd];
    int token = inp[b];
    cat[k] = emb[(size_t)token * Ed + k];
    cat[Ed + k] = g_Xa[b * Hd + k];
    __syncthreads();
    float acc = b3[k];
#pragma unroll 8
    for (int j = 0; j < Ed + Hd; j++) acc += cat[j] * W3[j * Hd + k];
    g_res[b * Hd + k] = acc;
}

// ---------------- K5: GRU cell (PyTorch gate order r,z,n) ----------------
__global__ void gru_kernel(const float* __restrict__ hidden_in,
                           const float* __restrict__ Wih,
                           const float* __restrict__ Whh,
                           const float* __restrict__ bih,
                           const float* __restrict__ bhh,
                           int cell,
                           float* __restrict__ hidden_out) {
    const int b = blockIdx.x;
    const int tid = threadIdx.x;  // 768
    __shared__ float sx[Hd], sh[Hd], sgi[3 * Hd], sgh[3 * Hd];
    const float* x = (cell == 0) ? g_res : g_h0;
    if (tid < Hd) {
        sx[tid] = x[b * Hd + tid];
        sh[tid] = hidden_in[((size_t)cell * Bd + b) * Hd + tid];
    }
    __syncthreads();
    {
        int g = tid;
        const float4* wi = (const float4*)(Wih + (size_t)g * Hd);
        const float4* wh = (const float4*)(Whh + (size_t)g * Hd);
        float gi = bih[g], gh = bhh[g];
#pragma unroll 8
        for (int q = 0; q < Hd / 4; q++) {
            float4 a = wi[q];
            float4 c = wh[q];
            float4 xv = *(const float4*)&sx[q * 4];
            float4 hv = *(const float4*)&sh[q * 4];
            gi += a.x * xv.x + a.y * xv.y + a.z * xv.z + a.w * xv.w;
            gh += c.x * hv.x + c.y * hv.y + c.z * hv.z + c.w * hv.w;
        }
        sgi[g] = gi;
        sgh[g] = gh;
    }
    __syncthreads();
    if (tid < Hd) {
        int j = tid;
        float r = 1.f / (1.f + expf(-(sgi[j] + sgh[j])));
        float z = 1.f / (1.f + expf(-(sgi[Hd + j] + sgh[Hd + j])));
        float n = tanhf(sgi[2 * Hd + j] + r * sgh[2 * Hd + j]);
        float hn = (1.f - z) * n + z * sh[j];
        float* ho = (cell == 0) ? g_h0 : g_h1;
        ho[b * Hd + j] = hn;
        hidden_out[((size_t)cell * Bd + b) * Hd + j] = hn;  // new_hidden
    }
}

// ---------------- K6: h1 transpose for coalesced logits GEMM ----------------
__global__ void transpose_kernel() {
    int b = blockIdx.x;
    int h = threadIdx.x;
    g_h1T[h * Bd + b] = g_h1[b * Hd + h];
}

// ---------------- K7: logits = h1 @ Wout^T + bout -> d_out ----------------
// Block: 64 v-rows x all 128 b. Thread (16x16): 4 v x 8 b (4 float2). FFMA2.
__global__ __launch_bounds__(256)
void logits_kernel(const float* __restrict__ Wout,
                   const float* __restrict__ bout,
                   float* __restrict__ out) {
    __shared__ float wout_s[64 * 64];   // [v][k]
    __shared__ float h1s[64 * 128];     // [k][b]; reused for output staging
    const int v0 = blockIdx.x * 64;
    const int tid = threadIdx.x;
    const int tx = tid & 15;
    const int ty = tid >> 4;

    u64 acc[4][4];
#pragma unroll
    for (int i = 0; i < 4; i++)
#pragma unroll
        for (int j = 0; j < 4; j++) acc[i][j] = 0ull;

    for (int kk = 0; kk < Hd; kk += 64) {
#pragma unroll
        for (int t = 0; t < 4; t++) {
            int q = tid + t * 256;  // float4 idx, 1024 total
            int row = q >> 4;
            int c4 = (q & 15) * 4;
            *(float4*)&wout_s[row * 64 + c4] =
                *(const float4*)(Wout + (size_t)(v0 + row) * Hd + kk + c4);
        }
#pragma unroll
        for (int t = 0; t < 8; t++) {
            int q = tid + t * 256;  // float4 idx, 2048 total
            int row = q >> 5;
            int c4 = (q & 31) * 4;
            *(float4*)&h1s[row * 128 + c4] =
                *(const float4*)(g_h1T + (size_t)(kk + row) * Bd + c4);
        }
        __syncthreads();
#pragma unroll 8
        for (int k = 0; k < 64; k++) {
            u64 av[4];
#pragma unroll
            for (int i = 0; i < 4; i++) {
                float a = wout_s[(ty * 4 + i) * 64 + k];
                av[i] = pack2(a, a);
            }
#pragma unroll
            for (int j = 0; j < 4; j++) {
                u64 bv = *(const u64*)&h1s[k * 128 + tx * 2 + j * 32];
#pragma unroll
                for (int i = 0; i < 4; i++) acc[i][j] = ffma2(av[i], bv, acc[i][j]);
            }
        }
        __syncthreads();
    }

    // stage tile [b][v] in smem, then coalesced global writes
#pragma unroll
    for (int i = 0; i < 4; i++)
#pragma unroll
        for (int j = 0; j < 4; j++) {
            float2 a = unpack2(acc[i][j]);
            int v = ty * 4 + i;
            int bb = tx * 2 + j * 32;
            h1s[bb * 64 + v] = a.x;
            h1s[(bb + 1) * 64 + v] = a.y;
        }
    __syncthreads();
    for (int q = tid; q < 8192; q += 256) {
        int bb = q >> 6;
        int v = q & 63;
        out[(size_t)bb * VSZ + v0 + v] = h1s[q] + bout[v0 + v];
    }
}

// ---------------- K8: in-place log_softmax over vocab ----------------
__global__ void logsoftmax_kernel(float* __restrict__ out) {
    const int b = blockIdx.x;
    const int tid = threadIdx.x;  // 512
    __shared__ float red[512];
    float* row = out + (size_t)b * VSZ;

    float m = -1e30f;
    for (int v = tid; v < VSZ; v += 512) m = fmaxf(m, row[v]);
    red[tid] = m;
    __syncthreads();
    for (int d = 256; d > 0; d >>= 1) {
        if (tid < d) red[tid] = fmaxf(red[tid], red[tid + d]);
        __syncthreads();
    }
    m = red[0];
    __syncthreads();

    float s = 0.f;
    for (int v = tid; v < VSZ; v += 512) s += expf(row[v] - m);
    red[tid] = s;
    __syncthreads();
    for (int d = 256; d > 0; d >>= 1) {
        if (tid < d) red[tid] += red[tid + d];
        __syncthreads();
    }
    float lse = m + logf(red[0]);
    for (int v = tid; v < VSZ; v += 512) row[v] -= lse;
}

// ---------------- launch ----------------
extern "C" void kernel_launch(void* const* d_in, const int* in_sizes, int n_in,
                              void* d_out, int out_size) {
    const int* inp = (const int*)d_in[0];
    const float* hidden = (const float*)d_in[1];
    const float* enc = (const float*)d_in[2];
    const float* emb = (const float*)d_in[3];
    const float* W1 = (const float*)d_in[4];
    const float* W2 = (const float*)d_in[5];
    const float* W3 = (const float*)d_in[6];
    const float* b2 = (const float*)d_in[7];
    const float* b3 = (const float*)d_in[8];
    const float* V = (const float*)d_in[9];
    const float* Wih0 = (const float*)d_in[10];
    const float* Whh0 = (const float*)d_in[11];
    const float* bih0 = (const float*)d_in[12];
    const float* bhh0 = (const float*)d_in[13];
    const float* Wih1 = (const float*)d_in[14];
    const float* Whh1 = (const float*)d_in[15];
    const float* bih1 = (const float*)d_in[16];
    const float* bhh1 = (const float*)d_in[17];
    const float* Wout = (const float*)d_in[18];
    const float* bout = (const float*)d_in[19];

    float* out = (float*)d_out;                       // [B, VSZ] log-probs
    float* hid_out = out + (size_t)Bd * VSZ;          // [2, B, H] new_hidden

    w2h_kernel<<<Bd, Hd>>>(hidden, W2, b2);
    scores_kernel<<<dim3(Sd / 64, Bd), 256>>>(enc, W1, V);
    attn_kernel<<<Bd, 256>>>(enc);
    res_kernel<<<Bd, Hd>>>(inp, emb, W3, b3);
    gru_kernel<<<Bd, 768>>>(hidden, Wih0, Whh0, bih0, bhh0, 0, hid_out);
    gru_kernel<<<Bd, 768>>>(hidden, Wih1, Whh1, bih1, bhh1, 1, hid_out);
    transpose_kernel<<<Bd, Hd>>>();
    logits_kernel<<<VSZ / 64, 256>>>(Wout, bout, out);
    logsoftmax_kernel<<<Bd, 512>>>(out);
}

// round 3
// speedup vs baseline: 1.7201x; 1.7201x over previous
#include <cuda_runtime.h>
#include <cuda_bf16.h>
#include <cstdint>

#define Bd 128
#define Sd 2048
#define Hd 256
#define Ed 256
#define VSZ 32000

// ---------------- scratch (device globals; no allocation) ----------------
__device__ float g_w2h[Bd * Hd];
__device__ float g_scores[Bd * Sd];
__device__ float g_Xa[Bd * Hd];
__device__ float g_res[Bd * Hd];
__device__ float g_h0[Bd * Hd];
__device__ float g_h1[Bd * Hd];
__device__ float g_h1T[Hd * Bd];

// W1 pre-packed for the scores GEMM:
// 4 k-chunks; per chunk: hi block then lo block, each 256 n-rows x 72 bf16
// (64 data + 8 pad -> 144B rows for conflict-free fragment LDS).
#define PAD_E 72
#define CH_HALF_E (Hd * PAD_E)           // 18432 elems = 36864 B
#define CH_E (2 * CH_HALF_E)             // hi + lo per chunk
__device__ __align__(16) __nv_bfloat16 g_W1p[4 * CH_E];

typedef unsigned long long u64;

// ---------------- helpers ----------------
__device__ __forceinline__ u64 pack2(float x, float y) {
    u64 d;
    asm("mov.b64 %0, {%1, %2};" : "=l"(d)
        : "r"(__float_as_uint(x)), "r"(__float_as_uint(y)));
    return d;
}
__device__ __forceinline__ u64 ffma2(u64 a, u64 b, u64 c) {
    u64 d;
    asm("fma.rn.f32x2 %0, %1, %2, %3;" : "=l"(d) : "l"(a), "l"(b), "l"(c));
    return d;
}
__device__ __forceinline__ float2 unpack2(u64 v) {
    unsigned lo, hi;
    asm("mov.b64 {%0, %1}, %2;" : "=r"(lo), "=r"(hi) : "l"(v));
    float2 r;
    r.x = __uint_as_float(lo);
    r.y = __uint_as_float(hi);
    return r;
}
__device__ __forceinline__ float fast_tanh(float x) {
    float y;
    asm("tanh.approx.f32 %0, %1;" : "=f"(y) : "f"(x));
    return y;
}
__device__ __forceinline__ void mma_bf16(float* d, const uint32_t* a,
                                         uint32_t b0, uint32_t b1) {
    asm volatile(
        "mma.sync.aligned.m16n8k16.row.col.f32.bf16.bf16.f32 "
        "{%0,%1,%2,%3}, {%4,%5,%6,%7}, {%8,%9}, {%0,%1,%2,%3};"
        : "+f"(d[0]), "+f"(d[1]), "+f"(d[2]), "+f"(d[3])
        : "r"(a[0]), "r"(a[1]), "r"(a[2]), "r"(a[3]), "r"(b0), "r"(b1));
}

// ---------------- P0: pack W1 (transpose + bf16 hi/lo split, padded) -------
__global__ void prep_w1_kernel(const float* __restrict__ W1) {
    int n = blockIdx.x;   // output col of GEMM (W1 column)
    int k = threadIdx.x;  // contraction index
    float x = W1[k * Hd + n];
    __nv_bfloat16 h = __float2bfloat16_rn(x);
    __nv_bfloat16 l = __float2bfloat16_rn(x - __bfloat162float(h));
    int c = k >> 6;
    int kk = k & 63;
    g_W1p[c * CH_E + n * PAD_E + kk] = h;
    g_W1p[c * CH_E + CH_HALF_E + n * PAD_E + kk] = l;
}

// ---------------- K1: w2h = hidden[1] @ W2 + b2 ----------------
__global__ void w2h_kernel(const float* __restrict__ hidden,
                           const float* __restrict__ W2,
                           const float* __restrict__ b2) {
    int b = blockIdx.x;
    int tid = threadIdx.x;  // 512
    int k = tid & 255;
    int h = tid >> 8;
    __shared__ float sh[Hd];
    __shared__ float part[512];
    if (tid < Hd) sh[tid] = hidden[(Bd + b) * Hd + tid];
    __syncthreads();
    float acc = 0.f;
#pragma unroll 16
    for (int j = h * 128; j < h * 128 + 128; j++) acc += sh[j] * W2[j * Hd + k];
    part[tid] = acc;
    __syncthreads();
    if (tid < 256) g_w2h[b * Hd + tid] = part[tid] + part[tid + 256] + b2[tid];
}

// ---------------- K2: scores via mma.sync bf16 3-MMA split ----------------
// CTA: 128 m-rows x 256 n. 8 warps = 4m x 2n; warp tile 32m x 128n.
// K=256 in 4 chunks of 64. A (enc) converted inline; B from g_W1p memcpy.
// SMEM: A hi [128x144B]=18432, A lo +18432 (total 36864);
//       B at 36864: hi 36864 + lo 36864. Total 110592.
#define A_HI 0
#define A_LO 18432
#define B_OFF 36864
#define B_LO_OFF (36864 + 36864)
#define SC_SMEM 110592
__global__ __launch_bounds__(256, 1)
void scores_mma_kernel(const float* __restrict__ enc,
                       const float* __restrict__ Vv) {
    extern __shared__ __align__(16) char smem[];
    const int tid = threadIdx.x;
    const int wid = tid >> 5;
    const int lane = tid & 31;
    const int g = lane >> 2;
    const int t = lane & 3;
    const int wm = wid >> 1;  // 0..3 (m group of 32)
    const int wn = wid & 1;   // 0..1 (n half of 128)
    const int m0 = blockIdx.x * 128;
    const int b = m0 >> 11;
    const int s0 = m0 & (Sd - 1);

    float acc[2][16][4];
#pragma unroll
    for (int f = 0; f < 2; f++)
#pragma unroll
        for (int j = 0; j < 16; j++)
#pragma unroll
            for (int q = 0; q < 4; q++) acc[f][j][q] = 0.f;

    const float* encb = enc + (size_t)m0 * Hd;

    for (int c = 0; c < 4; c++) {
        // ---- fill B: straight contiguous copy of packed chunk (73728 B) ----
        {
            const uint4* src = (const uint4*)(g_W1p + (size_t)c * CH_E);
            uint4* dst = (uint4*)(smem + B_OFF);
#pragma unroll
            for (int i = 0; i < 18; i++) dst[tid + i * 256] = src[tid + i * 256];
        }
        // ---- fill A: 128 rows x 64 k fp32 -> bf16 hi/lo, padded rows ----
        {
#pragma unroll
            for (int i = 0; i < 16; i++) {
                int idx = tid + i * 256;          // 4096 float2
                int row = idx >> 5;
                int kp = idx & 31;                // float2 index in k
                float2 v = *(const float2*)(encb + (size_t)row * Hd + c * 64 + kp * 2);
                __nv_bfloat16 h0 = __float2bfloat16_rn(v.x);
                __nv_bfloat16 h1 = __float2bfloat16_rn(v.y);
                __nv_bfloat16 l0 = __float2bfloat16_rn(v.x - __bfloat162float(h0));
                __nv_bfloat16 l1 = __float2bfloat16_rn(v.y - __bfloat162float(h1));
                __nv_bfloat162 hp = {h0, h1};
                __nv_bfloat162 lp = {l0, l1};
                uint32_t off = row * 144 + kp * 4;
                *(uint32_t*)(smem + A_HI + off) = *(uint32_t*)&hp;
                *(uint32_t*)(smem + A_LO + off) = *(uint32_t*)&lp;
            }
        }
        __syncthreads();

        // ---- compute: 4 k-steps of 16 ----
#pragma unroll
        for (int s = 0; s < 4; s++) {
            uint32_t ah[2][4], al[2][4];
#pragma unroll
            for (int f = 0; f < 2; f++) {
                int r0 = wm * 32 + f * 16 + g;
                uint32_t o0 = r0 * 144 + s * 32 + t * 4;
                uint32_t o1 = (r0 + 8) * 144 + s * 32 + t * 4;
                ah[f][0] = *(const uint32_t*)(smem + A_HI + o0);
                ah[f][1] = *(const uint32_t*)(smem + A_HI + o1);
                ah[f][2] = *(const uint32_t*)(smem + A_HI + o0 + 16);
                ah[f][3] = *(const uint32_t*)(smem + A_HI + o1 + 16);
                al[f][0] = *(const uint32_t*)(smem + A_LO + o0);
                al[f][1] = *(const uint32_t*)(smem + A_LO + o1);
                al[f][2] = *(const uint32_t*)(smem + A_LO + o0 + 16);
                al[f][3] = *(const uint32_t*)(smem + A_LO + o1 + 16);
            }
#pragma unroll
            for (int j = 0; j < 16; j++) {
                int n = wn * 128 + 8 * j + g;
                uint32_t bo = n * 144 + s * 32 + t * 4;
                uint32_t bh0 = *(const uint32_t*)(smem + B_OFF + bo);
                uint32_t bh1 = *(const uint32_t*)(smem + B_OFF + bo + 16);
                uint32_t bl0 = *(const uint32_t*)(smem + B_LO_OFF + bo);
                uint32_t bl1 = *(const uint32_t*)(smem + B_LO_OFF + bo + 16);
#pragma unroll
                for (int f = 0; f < 2; f++) {
                    mma_bf16(acc[f][j], ah[f], bh0, bh1);
                    mma_bf16(acc[f][j], al[f], bh0, bh1);
                    mma_bf16(acc[f][j], ah[f], bl0, bl1);
                }
            }
        }
        __syncthreads();
    }

    // ---- epilogue: score[m] = sum_n V[n] * tanh(D[m][n] + w2h[b][n]) ----
    float* sw2 = (float*)smem;            // 256 f
    float* sV = (float*)(smem + 1024);    // 256 f
    float* sp = (float*)(smem + 2048);    // 256 f (2 n-halves x 128 rows)
    sw2[tid] = g_w2h[b * Hd + tid];
    sV[tid] = Vv[tid];
    __syncthreads();

    float p[2][2] = {{0.f, 0.f}, {0.f, 0.f}};  // [f][u] rows g / g+8
#pragma unroll
    for (int f = 0; f < 2; f++)
#pragma unroll
        for (int j = 0; j < 16; j++) {
            int cc = wn * 128 + 8 * j + 2 * t;
            float v0 = sV[cc], v1 = sV[cc + 1];
            float w0 = sw2[cc], w1 = sw2[cc + 1];
            p[f][0] += v0 * fast_tanh(acc[f][j][0] + w0)
                     + v1 * fast_tanh(acc[f][j][1] + w1);
            p[f][1] += v0 * fast_tanh(acc[f][j][2] + w0)
                     + v1 * fast_tanh(acc[f][j][3] + w1);
        }
#pragma unroll
    for (int f = 0; f < 2; f++)
#pragma unroll
        for (int u = 0; u < 2; u++) {
            float v = p[f][u];
            v += __shfl_xor_sync(0xffffffffu, v, 1);
            v += __shfl_xor_sync(0xffffffffu, v, 2);
            if (t == 0) {
                int r = wm * 32 + f * 16 + g + 8 * u;
                sp[wn * 128 + r] = v;
            }
        }
    __syncthreads();
    if (tid < 128) g_scores[b * Sd + s0 + tid] = sp[tid] + sp[128 + tid];
}

// ---------------- K3: softmax over S + Xa = a . enc ----------------
__global__ void attn_kernel(const float* __restrict__ enc) {
    const int b = blockIdx.x;
    const int tid = threadIdx.x;  // 256
    __shared__ float sa[Sd];
    __shared__ float red[256];

    float m = -1e30f;
    for (int s = tid; s < Sd; s += 256) {
        float v = g_scores[b * Sd + s];
        sa[s] = v;
        m = fmaxf(m, v);
    }
    red[tid] = m;
    __syncthreads();
    for (int d = 128; d > 0; d >>= 1) {
        if (tid < d) red[tid] = fmaxf(red[tid], red[tid + d]);
        __syncthreads();
    }
    m = red[0];
    __syncthreads();

    float sum = 0.f;
    for (int s = tid; s < Sd; s += 256) {
        float e = expf(sa[s] - m);
        sa[s] = e;
        sum += e;
    }
    red[tid] = sum;
    __syncthreads();
    for (int d = 128; d > 0; d >>= 1) {
        if (tid < d) red[tid] += red[tid + d];
        __syncthreads();
    }
    float inv = 1.f / red[0];

    int h = tid;
    const float* eb = enc + (size_t)b * Sd * Hd + h;
    float acc = 0.f;
#pragma unroll 8
    for (int s = 0; s < Sd; s++) acc += sa[s] * eb[(size_t)s * Hd];
    g_Xa[b * Hd + h] = acc * inv;
}

// ---------------- K4: res = [emb[inp]; Xa] @ W3 + b3 ----------------
__global__ void res_kernel(const int* __restrict__ inp,
                           const float* __restrict__ emb,
                           const float* __restrict__ W3,
                           const float* __restrict__ b3) {
    const int b = blockIdx.x;
    const int tid = threadIdx.x;  // 512
    const int k = tid & 255;
    const int h = tid >> 8;
    __shared__ float cat[Ed + Hd];
    __shared__ float part[512];
    int token = inp[b];
    if (tid < Ed) cat[tid] = emb[(size_t)token * Ed + tid];
    else cat[tid] = g_Xa[b * Hd + (tid - Ed)];
    __syncthreads();
    float acc = 0.f;
#pragma unroll 16
    for (int j = h * 256; j < h * 256 + 256; j++) acc += cat[j] * W3[j * Hd + k];
    part[tid] = acc;
    __syncthreads();
    if (tid < 256) g_res[b * Hd + tid] = part[tid] + part[tid + 256] + b3[tid];
}

// ---------------- K5: GRU cell (gate order r,z,n) ----------------
__global__ void gru_kernel(const float* __restrict__ hidden_in,
                           const float* __restrict__ Wih,
                           const float* __restrict__ Whh,
                           const float* __restrict__ bih,
                           const float* __restrict__ bhh,
                           int cell,
                           float* __restrict__ hidden_out) {
    const int b = blockIdx.x;
    const int tid = threadIdx.x;  // 768
    __shared__ float sx[Hd], sh[Hd], sgi[3 * Hd], sgh[3 * Hd];
    const float* x = (cell == 0) ? g_res : g_h0;
    if (tid < Hd) {
        sx[tid] = x[b * Hd + tid];
        sh[tid] = hidden_in[((size_t)cell * Bd + b) * Hd + tid];
    }
    __syncthreads();
    {
        int g = tid;
        const float4* wi = (const float4*)(Wih + (size_t)g * Hd);
        const float4* wh = (const float4*)(Whh + (size_t)g * Hd);
        float gi = bih[g], gh = bhh[g];
#pragma unroll 16
        for (int q = 0; q < Hd / 4; q++) {
            float4 a = wi[q];
            float4 c = wh[q];
            float4 xv = *(const float4*)&sx[q * 4];
            float4 hv = *(const float4*)&sh[q * 4];
            gi += a.x * xv.x + a.y * xv.y + a.z * xv.z + a.w * xv.w;
            gh += c.x * hv.x + c.y * hv.y + c.z * hv.z + c.w * hv.w;
        }
        sgi[g] = gi;
        sgh[g] = gh;
    }
    __syncthreads();
    if (tid < Hd) {
        int j = tid;
        float r = 1.f / (1.f + expf(-(sgi[j] + sgh[j])));
        float z = 1.f / (1.f + expf(-(sgi[Hd + j] + sgh[Hd + j])));
        float n = tanhf(sgi[2 * Hd + j] + r * sgh[2 * Hd + j]);
        float hn = (1.f - z) * n + z * sh[j];
        float* ho = (cell == 0) ? g_h0 : g_h1;
        ho[b * Hd + j] = hn;
        hidden_out[((size_t)cell * Bd + b) * Hd + j] = hn;
    }
}

// ---------------- K6: h1 transpose ----------------
__global__ void transpose_kernel() {
    int b = blockIdx.x;
    int h = threadIdx.x;
    g_h1T[h * Bd + b] = g_h1[b * Hd + h];
}

// ---------------- K7: logits = h1 @ Wout^T + bout ----------------
__global__ __launch_bounds__(256)
void logits_kernel(const float* __restrict__ Wout,
                   const float* __restrict__ bout,
                   float* __restrict__ out) {
    __shared__ float wout_s[64 * 64];
    __shared__ float h1s[64 * 128];
    const int v0 = blockIdx.x * 64;
    const int tid = threadIdx.x;
    const int tx = tid & 15;
    const int ty = tid >> 4;

    u64 acc[4][4];
#pragma unroll
    for (int i = 0; i < 4; i++)
#pragma unroll
        for (int j = 0; j < 4; j++) acc[i][j] = 0ull;

    for (int kk = 0; kk < Hd; kk += 64) {
#pragma unroll
        for (int t = 0; t < 4; t++) {
            int q = tid + t * 256;
            int row = q >> 4;
            int c4 = (q & 15) * 4;
            *(float4*)&wout_s[row * 64 + c4] =
                *(const float4*)(Wout + (size_t)(v0 + row) * Hd + kk + c4);
        }
#pragma unroll
        for (int t = 0; t < 8; t++) {
            int q = tid + t * 256;
            int row = q >> 5;
            int c4 = (q & 31) * 4;
            *(float4*)&h1s[row * 128 + c4] =
                *(const float4*)(g_h1T + (size_t)(kk + row) * Bd + c4);
        }
        __syncthreads();
#pragma unroll 8
        for (int k = 0; k < 64; k++) {
            u64 av[4];
#pragma unroll
            for (int i = 0; i < 4; i++) {
                float a = wout_s[(ty * 4 + i) * 64 + k];
                av[i] = pack2(a, a);
            }
#pragma unroll
            for (int j = 0; j < 4; j++) {
                u64 bv = *(const u64*)&h1s[k * 128 + tx * 2 + j * 32];
#pragma unroll
                for (int i = 0; i < 4; i++) acc[i][j] = ffma2(av[i], bv, acc[i][j]);
            }
        }
        __syncthreads();
    }

#pragma unroll
    for (int i = 0; i < 4; i++)
#pragma unroll
        for (int j = 0; j < 4; j++) {
            float2 a = unpack2(acc[i][j]);
            int v = ty * 4 + i;
            int bb = tx * 2 + j * 32;
            h1s[bb * 64 + v] = a.x;
            h1s[(bb + 1) * 64 + v] = a.y;
        }
    __syncthreads();
    for (int q = tid; q < 8192; q += 256) {
        int bb = q >> 6;
        int v = q & 63;
        out[(size_t)bb * VSZ + v0 + v] = h1s[q] + bout[v0 + v];
    }
}

// ---------------- K8: in-place log_softmax over vocab ----------------
__global__ void logsoftmax_kernel(float* __restrict__ out) {
    const int b = blockIdx.x;
    const int tid = threadIdx.x;  // 512
    __shared__ float red[512];
    float* row = out + (size_t)b * VSZ;

    float m = -1e30f;
    for (int v = tid; v < VSZ; v += 512) m = fmaxf(m, row[v]);
    red[tid] = m;
    __syncthreads();
    for (int d = 256; d > 0; d >>= 1) {
        if (tid < d) red[tid] = fmaxf(red[tid], red[tid + d]);
        __syncthreads();
    }
    m = red[0];
    __syncthreads();

    float s = 0.f;
    for (int v = tid; v < VSZ; v += 512) s += expf(row[v] - m);
    red[tid] = s;
    __syncthreads();
    for (int d = 256; d > 0; d >>= 1) {
        if (tid < d) red[tid] += red[tid + d];
        __syncthreads();
    }
    float lse = m + logf(red[0]);
    for (int v = tid; v < VSZ; v += 512) row[v] -= lse;
}

// ---------------- launch ----------------
extern "C" void kernel_launch(void* const* d_in, const int* in_sizes, int n_in,
                              void* d_out, int out_size) {
    const int* inp = (const int*)d_in[0];
    const float* hidden = (const float*)d_in[1];
    const float* enc = (const float*)d_in[2];
    const float* emb = (const float*)d_in[3];
    const float* W1 = (const float*)d_in[4];
    const float* W2 = (const float*)d_in[5];
    const float* W3 = (const float*)d_in[6];
    const float* b2 = (const float*)d_in[7];
    const float* b3 = (const float*)d_in[8];
    const float* V = (const float*)d_in[9];
    const float* Wih0 = (const float*)d_in[10];
    const float* Whh0 = (const float*)d_in[11];
    const float* bih0 = (const float*)d_in[12];
    const float* bhh0 = (const float*)d_in[13];
    const float* Wih1 = (const float*)d_in[14];
    const float* Whh1 = (const float*)d_in[15];
    const float* bih1 = (const float*)d_in[16];
    const float* bhh1 = (const float*)d_in[17];
    const float* Wout = (const float*)d_in[18];
    const float* bout = (const float*)d_in[19];

    float* out = (float*)d_out;
    float* hid_out = out + (size_t)Bd * VSZ;

    cudaFuncSetAttribute(scores_mma_kernel,
                         cudaFuncAttributeMaxDynamicSharedMemorySize, SC_SMEM);

    prep_w1_kernel<<<Hd, Hd>>>(W1);
    w2h_kernel<<<Bd, 512>>>(hidden, W2, b2);
    scores_mma_kernel<<<(Bd * Sd) / 128, 256, SC_SMEM>>>(enc, V);
    attn_kernel<<<Bd, 256>>>(enc);
    res_kernel<<<Bd, 512>>>(inp, emb, W3, b3);
    gru_kernel<<<Bd, 768>>>(hidden, Wih0, Whh0, bih0, bhh0, 0, hid_out);
    gru_kernel<<<Bd, 768>>>(hidden, Wih1, Whh1, bih1, bhh1, 1, hid_out);
    transpose_kernel<<<Bd, Hd>>>();
    logits_kernel<<<VSZ / 64, 256>>>(Wout, bout, out);
    logsoftmax_kernel<<<Bd, 512>>>(out);
}

// round 4
// speedup vs baseline: 3.1278x; 1.8183x over previous
#include <cuda_runtime.h>
#include <cuda_bf16.h>
#include <cstdint>

#define Bd 128
#define Sd 2048
#define Hd 256
#define Ed 256
#define VSZ 32000

// ---------------- scratch (device globals; no allocation) ----------------
__device__ float g_w2h[Bd * Hd];
__device__ float g_scores[Bd * Sd];
__device__ float g_XaP[16 * Bd * Hd];   // split-S partials for Xa
__device__ float g_res[Bd * Hd];
__device__ float g_h0[Bd * Hd];
__device__ float g_h1[Bd * Hd];
__device__ float g_h1T[Hd * Bd];

// W1 pre-packed: 4 k-chunks; per chunk: hi block then lo block, each
// 256 n-rows x 72 bf16 (64 data + 8 pad -> 144B rows, conflict-free LDS).
#define PAD_E 72
#define CH_HALF_E (Hd * PAD_E)           // 18432 elems = 36864 B
#define CH_E (2 * CH_HALF_E)
__device__ __align__(16) __nv_bfloat16 g_W1p[4 * CH_E];

typedef unsigned long long u64;

// ---------------- helpers ----------------
__device__ __forceinline__ u64 pack2(float x, float y) {
    u64 d;
    asm("mov.b64 %0, {%1, %2};" : "=l"(d)
        : "r"(__float_as_uint(x)), "r"(__float_as_uint(y)));
    return d;
}
__device__ __forceinline__ u64 ffma2(u64 a, u64 b, u64 c) {
    u64 d;
    asm("fma.rn.f32x2 %0, %1, %2, %3;" : "=l"(d) : "l"(a), "l"(b), "l"(c));
    return d;
}
__device__ __forceinline__ float2 unpack2(u64 v) {
    unsigned lo, hi;
    asm("mov.b64 {%0, %1}, %2;" : "=r"(lo), "=r"(hi) : "l"(v));
    float2 r;
    r.x = __uint_as_float(lo);
    r.y = __uint_as_float(hi);
    return r;
}
__device__ __forceinline__ float fast_tanh(float x) {
    float y;
    asm("tanh.approx.f32 %0, %1;" : "=f"(y) : "f"(x));
    return y;
}
__device__ __forceinline__ uint32_t smem_u32(const void* p) {
    uint32_t a;
    asm("{ .reg .u64 t; cvta.to.shared.u64 t, %1; cvt.u32.u64 %0, t; }"
        : "=r"(a) : "l"(p));
    return a;
}
__device__ __forceinline__ void cp16(uint32_t dst, const void* src) {
    asm volatile("cp.async.cg.shared.global [%0], [%1], 16;"
                 :: "r"(dst), "l"(src) : "memory");
}
__device__ __forceinline__ void cp_commit() {
    asm volatile("cp.async.commit_group;" ::: "memory");
}
template <int N>
__device__ __forceinline__ void cp_wait() {
    asm volatile("cp.async.wait_group %0;" :: "n"(N) : "memory");
}
__device__ __forceinline__ void mma_bf16(float* d, const uint32_t* a,
                                         uint32_t b0, uint32_t b1) {
    asm volatile(
        "mma.sync.aligned.m16n8k16.row.col.f32.bf16.bf16.f32 "
        "{%0,%1,%2,%3}, {%4,%5,%6,%7}, {%8,%9}, {%0,%1,%2,%3};"
        : "+f"(d[0]), "+f"(d[1]), "+f"(d[2]), "+f"(d[3])
        : "r"(a[0]), "r"(a[1]), "r"(a[2]), "r"(a[3]), "r"(b0), "r"(b1));
}

// ---------------- P0: pack W1 (transpose + bf16 hi/lo split, padded) -------
__global__ void prep_w1_kernel(const float* __restrict__ W1) {
    int n = blockIdx.x;
    int k = threadIdx.x;
    float x = W1[k * Hd + n];
    __nv_bfloat16 h = __float2bfloat16_rn(x);
    __nv_bfloat16 l = __float2bfloat16_rn(x - __bfloat162float(h));
    int c = k >> 6;
    int kk = k & 63;
    g_W1p[c * CH_E + n * PAD_E + kk] = h;
    g_W1p[c * CH_E + CH_HALF_E + n * PAD_E + kk] = l;
}

// ---------------- K1: w2h = hidden[1] @ W2 + b2 ----------------
__global__ void w2h_kernel(const float* __restrict__ hidden,
                           const float* __restrict__ W2,
                           const float* __restrict__ b2) {
    int b = blockIdx.x;
    int tid = threadIdx.x;  // 512
    int k = tid & 255;
    int h = tid >> 8;
    __shared__ float sh[Hd];
    __shared__ float part[512];
    if (tid < Hd) sh[tid] = hidden[(Bd + b) * Hd + tid];
    __syncthreads();
    float acc = 0.f;
#pragma unroll 16
    for (int j = h * 128; j < h * 128 + 128; j++) acc += sh[j] * W2[j * Hd + k];
    part[tid] = acc;
    __syncthreads();
    if (tid < 256) g_w2h[b * Hd + tid] = part[tid] + part[tid + 256] + b2[tid];
}

// ---------------- K2: scores via mma.sync, A resident + cp.async pipeline --
// CTA: 128m x 256n; 8 warps = 4m x 2n; warp tile 32m x 128n.
// SMEM: A hi [128 x 528B rows] = 67584; A lo +67584 (135168 total);
//       B: 2 x 36864 double-buffered chunk-halves at 135168.
// 8 B-stages: (chunk 0..3) x (hi, lo). hi-stage: ah*bh + al*bh; lo: ah*bl.
#define SA_HI 0
#define SA_LO 67584
#define SB_OFF 135168
#define SB_STRIDE 36864
#define SC_SMEM (135168 + 2 * 36864)
__global__ __launch_bounds__(256, 1)
void scores_mma_kernel(const float* __restrict__ enc,
                       const float* __restrict__ Vv) {
    extern __shared__ __align__(16) char smem[];
    const uint32_t sm_b = smem_u32(smem);
    const int tid = threadIdx.x;
    const int wid = tid >> 5;
    const int lane = tid & 31;
    const int g = lane >> 2;
    const int t = lane & 3;
    const int wm = wid >> 1;
    const int wn = wid & 1;
    const int m0 = blockIdx.x * 128;
    const int b = m0 >> 11;
    const int s0 = m0 & (Sd - 1);

    float acc[2][16][4];
#pragma unroll
    for (int f = 0; f < 2; f++)
#pragma unroll
        for (int j = 0; j < 16; j++)
#pragma unroll
            for (int q = 0; q < 4; q++) acc[f][j][q] = 0.f;

    // ---- issue B stage 0 (chunk 0, hi) ----
    {
        const char* src = (const char*)g_W1p;
#pragma unroll
        for (int i = 0; i < 9; i++) {
            int idx = tid + i * 256;
            cp16(sm_b + SB_OFF + idx * 16, src + idx * 16);
        }
        cp_commit();
    }

    // ---- fill A (entire 128 x 256, hi/lo), overlaps with cp.async ----
    {
        const float* encb = enc + (size_t)m0 * Hd;
#pragma unroll
        for (int i = 0; i < 16; i++) {
            int idx = tid + i * 256;        // 4096 float2
            int row = idx >> 5;
            int kp = idx & 31;              // float2 within 64-float2 row? no: 32 per i-block
            // each row has 128 float2; map: idx covers rows of 32 float2 at a time
            int rr = idx >> 7;              // 0..31 rows per... recompute properly below
            (void)rr;
            // Use direct mapping: 4096 entries = 128 rows x 32 float2 per quarter-row
            // We iterate k-quarters via i outer split instead:
            int row2 = (idx & 4095) / 32;   // 0..127
            int kq = i & 3;                 // not used
            (void)kq; (void)row; (void)kp; (void)row2;
            break;                           // replaced by explicit loop below
        }
        // explicit: 128 rows x 128 float2 = 16384 float2 -> 64 per thread
#pragma unroll
        for (int i = 0; i < 64; i++) {
            int idx = tid + i * 256;        // 16384 float2
            int row = idx >> 7;             // 128 float2 per row
            int kp = idx & 127;
            float2 v = *(const float2*)(encb + (size_t)row * Hd + kp * 2);
            __nv_bfloat16 h0 = __float2bfloat16_rn(v.x);
            __nv_bfloat16 h1 = __float2bfloat16_rn(v.y);
            __nv_bfloat16 l0 = __float2bfloat16_rn(v.x - __bfloat162float(h0));
            __nv_bfloat16 l1 = __float2bfloat16_rn(v.y - __bfloat162float(h1));
            __nv_bfloat162 hp = {h0, h1};
            __nv_bfloat162 lp = {l0, l1};
            uint32_t off = row * 528 + kp * 4;
            *(uint32_t*)(smem + SA_HI + off) = *(uint32_t*)&hp;
            *(uint32_t*)(smem + SA_LO + off) = *(uint32_t*)&lp;
        }
    }

    // ---- 8 pipelined B stages ----
#pragma unroll
    for (int s = 0; s < 8; s++) {
        if (s < 7) {
            int ns = s + 1;
            int nc = ns >> 1;
            int nh = ns & 1;
            const char* src = (const char*)g_W1p +
                              ((size_t)nc * CH_E + (size_t)nh * CH_HALF_E) * 2;
            uint32_t dst = sm_b + SB_OFF + (ns & 1) * SB_STRIDE;
#pragma unroll
            for (int i = 0; i < 9; i++) {
                int idx = tid + i * 256;
                cp16(dst + idx * 16, src + idx * 16);
            }
            cp_commit();
            cp_wait<1>();
        } else {
            cp_wait<0>();
        }
        __syncthreads();

        const int c = s >> 1;
        const bool hi = (s & 1) == 0;
        const char* Bb = smem + SB_OFF + (s & 1) * SB_STRIDE;

#pragma unroll
        for (int ks = 0; ks < 4; ks++) {
            uint32_t ah[2][4], al[2][4];
#pragma unroll
            for (int f = 0; f < 2; f++) {
                int r0 = wm * 32 + f * 16 + g;
                uint32_t o0 = r0 * 528 + c * 128 + ks * 32 + t * 4;
                uint32_t o1 = o0 + 8 * 528;
                ah[f][0] = *(const uint32_t*)(smem + SA_HI + o0);
                ah[f][1] = *(const uint32_t*)(smem + SA_HI + o1);
                ah[f][2] = *(const uint32_t*)(smem + SA_HI + o0 + 16);
                ah[f][3] = *(const uint32_t*)(smem + SA_HI + o1 + 16);
                if (hi) {
                    al[f][0] = *(const uint32_t*)(smem + SA_LO + o0);
                    al[f][1] = *(const uint32_t*)(smem + SA_LO + o1);
                    al[f][2] = *(const uint32_t*)(smem + SA_LO + o0 + 16);
                    al[f][3] = *(const uint32_t*)(smem + SA_LO + o1 + 16);
                }
            }
#pragma unroll
            for (int j = 0; j < 16; j++) {
                int n = wn * 128 + 8 * j + g;
                uint32_t bo = n * 144 + ks * 32 + t * 4;
                uint32_t b0 = *(const uint32_t*)(Bb + bo);
                uint32_t b1 = *(const uint32_t*)(Bb + bo + 16);
#pragma unroll
                for (int f = 0; f < 2; f++) {
                    mma_bf16(acc[f][j], ah[f], b0, b1);
                    if (hi) mma_bf16(acc[f][j], al[f], b0, b1);
                }
            }
        }
        __syncthreads();
    }

    // ---- epilogue: score[m] = sum_n V[n] * tanh(D[m][n] + w2h[b][n]) ----
    float* sw2 = (float*)smem;
    float* sV = (float*)(smem + 1024);
    float* sp = (float*)(smem + 2048);
    sw2[tid] = g_w2h[b * Hd + tid];
    sV[tid] = Vv[tid];
    __syncthreads();

    float p[2][2] = {{0.f, 0.f}, {0.f, 0.f}};
#pragma unroll
    for (int f = 0; f < 2; f++)
#pragma unroll
        for (int j = 0; j < 16; j++) {
            int cc = wn * 128 + 8 * j + 2 * t;
            float v0 = sV[cc], v1 = sV[cc + 1];
            float w0 = sw2[cc], w1 = sw2[cc + 1];
            p[f][0] += v0 * fast_tanh(acc[f][j][0] + w0)
                     + v1 * fast_tanh(acc[f][j][1] + w1);
            p[f][1] += v0 * fast_tanh(acc[f][j][2] + w0)
                     + v1 * fast_tanh(acc[f][j][3] + w1);
        }
#pragma unroll
    for (int f = 0; f < 2; f++)
#pragma unroll
        for (int u = 0; u < 2; u++) {
            float v = p[f][u];
            v += __shfl_xor_sync(0xffffffffu, v, 1);
            v += __shfl_xor_sync(0xffffffffu, v, 2);
            if (t == 0) {
                int r = wm * 32 + f * 16 + g + 8 * u;
                sp[wn * 128 + r] = v;
            }
        }
    __syncthreads();
    if (tid < 128) g_scores[b * Sd + s0 + tid] = sp[tid] + sp[128 + tid];
}

// ---------------- K3a: softmax over S (in-place -> probabilities) ---------
__global__ void softmax_kernel() {
    const int b = blockIdx.x;
    const int tid = threadIdx.x;  // 256
    __shared__ float sa[Sd];
    __shared__ float red[256];

    float m = -1e30f;
    for (int s = tid; s < Sd; s += 256) {
        float v = g_scores[b * Sd + s];
        sa[s] = v;
        m = fmaxf(m, v);
    }
    red[tid] = m;
    __syncthreads();
    for (int d = 128; d > 0; d >>= 1) {
        if (tid < d) red[tid] = fmaxf(red[tid], red[tid + d]);
        __syncthreads();
    }
    m = red[0];
    __syncthreads();

    float sum = 0.f;
    for (int s = tid; s < Sd; s += 256) {
        float e = expf(sa[s] - m);
        sa[s] = e;
        sum += e;
    }
    red[tid] = sum;
    __syncthreads();
    for (int d = 128; d > 0; d >>= 1) {
        if (tid < d) red[tid] += red[tid + d];
        __syncthreads();
    }
    float inv = 1.f / red[0];
    for (int s = tid; s < Sd; s += 256)
        g_scores[b * Sd + s] = sa[s] * inv;
}

// ---------------- K3b: Xa partials, split over 16 S-chunks ----------------
__global__ void xa_kernel(const float* __restrict__ enc) {
    const int chunk = blockIdx.x;
    const int b = blockIdx.y;
    const int tid = threadIdx.x;  // 256
    __shared__ float a_s[128];
    if (tid < 128) a_s[tid] = g_scores[b * Sd + chunk * 128 + tid];
    __syncthreads();
    const float* eb = enc + ((size_t)b * Sd + chunk * 128) * Hd + tid;
    float acc = 0.f;
#pragma unroll 8
    for (int s = 0; s < 128; s++) acc += a_s[s] * eb[(size_t)s * Hd];
    g_XaP[((size_t)chunk * Bd + b) * Hd + tid] = acc;
}

// ---------------- K4: res = [emb[inp]; Xa] @ W3 + b3 (Xa reduced here) ----
__global__ void res_kernel(const int* __restrict__ inp,
                           const float* __restrict__ emb,
                           const float* __restrict__ W3,
                           const float* __restrict__ b3) {
    const int b = blockIdx.x;
    const int tid = threadIdx.x;  // 512
    const int k = tid & 255;
    const int h = tid >> 8;
    __shared__ float cat[Ed + Hd];
    __shared__ float part[512];
    int token = inp[b];
    if (tid < Ed) {
        cat[tid] = emb[(size_t)token * Ed + tid];
    } else {
        int hh = tid - Ed;
        float x = 0.f;
#pragma unroll
        for (int i = 0; i < 16; i++)
            x += g_XaP[((size_t)i * Bd + b) * Hd + hh];
        cat[tid] = x;
    }
    __syncthreads();
    float acc = 0.f;
#pragma unroll 16
    for (int j = h * 256; j < h * 256 + 256; j++) acc += cat[j] * W3[j * Hd + k];
    part[tid] = acc;
    __syncthreads();
    if (tid < 256) g_res[b * Hd + tid] = part[tid] + part[tid + 256] + b3[tid];
}

// ---------------- K5: GRU cell (gate order r,z,n) ----------------
__global__ void gru_kernel(const float* __restrict__ hidden_in,
                           const float* __restrict__ Wih,
                           const float* __restrict__ Whh,
                           const float* __restrict__ bih,
                           const float* __restrict__ bhh,
                           int cell,
                           float* __restrict__ hidden_out) {
    const int b = blockIdx.x;
    const int tid = threadIdx.x;  // 768
    __shared__ float sx[Hd], sh[Hd], sgi[3 * Hd], sgh[3 * Hd];
    const float* x = (cell == 0) ? g_res : g_h0;
    if (tid < Hd) {
        sx[tid] = x[b * Hd + tid];
        sh[tid] = hidden_in[((size_t)cell * Bd + b) * Hd + tid];
    }
    __syncthreads();
    {
        int g = tid;
        const float4* wi = (const float4*)(Wih + (size_t)g * Hd);
        const float4* wh = (const float4*)(Whh + (size_t)g * Hd);
        float gi = bih[g], gh = bhh[g];
#pragma unroll 16
        for (int q = 0; q < Hd / 4; q++) {
            float4 a = wi[q];
            float4 c = wh[q];
            float4 xv = *(const float4*)&sx[q * 4];
            float4 hv = *(const float4*)&sh[q * 4];
            gi += a.x * xv.x + a.y * xv.y + a.z * xv.z + a.w * xv.w;
            gh += c.x * hv.x + c.y * hv.y + c.z * hv.z + c.w * hv.w;
        }
        sgi[g] = gi;
        sgh[g] = gh;
    }
    __syncthreads();
    if (tid < Hd) {
        int j = tid;
        float r = 1.f / (1.f + expf(-(sgi[j] + sgh[j])));
        float z = 1.f / (1.f + expf(-(sgi[Hd + j] + sgh[Hd + j])));
        float n = tanhf(sgi[2 * Hd + j] + r * sgh[2 * Hd + j]);
        float hn = (1.f - z) * n + z * sh[j];
        float* ho = (cell == 0) ? g_h0 : g_h1;
        ho[b * Hd + j] = hn;
        hidden_out[((size_t)cell * Bd + b) * Hd + j] = hn;
    }
}

// ---------------- K6: h1 transpose ----------------
__global__ void transpose_kernel() {
    int b = blockIdx.x;
    int h = threadIdx.x;
    g_h1T[h * Bd + b] = g_h1[b * Hd + h];
}

// ---------------- K7: logits = h1 @ Wout^T + bout ----------------
__global__ __launch_bounds__(256)
void logits_kernel(const float* __restrict__ Wout,
                   const float* __restrict__ bout,
                   float* __restrict__ out) {
    __shared__ float wout_s[64 * 64];
    __shared__ float h1s[64 * 128];
    const int v0 = blockIdx.x * 64;
    const int tid = threadIdx.x;
    const int tx = tid & 15;
    const int ty = tid >> 4;

    u64 acc[4][4];
#pragma unroll
    for (int i = 0; i < 4; i++)
#pragma unroll
        for (int j = 0; j < 4; j++) acc[i][j] = 0ull;

    for (int kk = 0; kk < Hd; kk += 64) {
#pragma unroll
        for (int t = 0; t < 4; t++) {
            int q = tid + t * 256;
            int row = q >> 4;
            int c4 = (q & 15) * 4;
            *(float4*)&wout_s[row * 64 + c4] =
                *(const float4*)(Wout + (size_t)(v0 + row) * Hd + kk + c4);
        }
#pragma unroll
        for (int t = 0; t < 8; t++) {
            int q = tid + t * 256;
            int row = q >> 5;
            int c4 = (q & 31) * 4;
            *(float4*)&h1s[row * 128 + c4] =
                *(const float4*)(g_h1T + (size_t)(kk + row) * Bd + c4);
        }
        __syncthreads();
#pragma unroll 8
        for (int k = 0; k < 64; k++) {
            u64 av[4];
#pragma unroll
            for (int i = 0; i < 4; i++) {
                float a = wout_s[(ty * 4 + i) * 64 + k];
                av[i] = pack2(a, a);
            }
#pragma unroll
            for (int j = 0; j < 4; j++) {
                u64 bv = *(const u64*)&h1s[k * 128 + tx * 2 + j * 32];
#pragma unroll
                for (int i = 0; i < 4; i++) acc[i][j] = ffma2(av[i], bv, acc[i][j]);
            }
        }
        __syncthreads();
    }

#pragma unroll
    for (int i = 0; i < 4; i++)
#pragma unroll
        for (int j = 0; j < 4; j++) {
            float2 a = unpack2(acc[i][j]);
            int v = ty * 4 + i;
            int bb = tx * 2 + j * 32;
            h1s[bb * 64 + v] = a.x;
            h1s[(bb + 1) * 64 + v] = a.y;
        }
    __syncthreads();
    for (int q = tid; q < 8192; q += 256) {
        int bb = q >> 6;
        int v = q & 63;
        out[(size_t)bb * VSZ + v0 + v] = h1s[q] + bout[v0 + v];
    }
}

// ---------------- K8: in-place log_softmax over vocab ----------------
__global__ __launch_bounds__(1024)
void logsoftmax_kernel(float* __restrict__ out) {
    const int b = blockIdx.x;
    const int tid = threadIdx.x;  // 1024
    __shared__ float red[1024];
    float* row = out + (size_t)b * VSZ;

    float m = -1e30f;
    for (int v = tid; v < VSZ; v += 1024) m = fmaxf(m, row[v]);
    red[tid] = m;
    __syncthreads();
    for (int d = 512; d > 0; d >>= 1) {
        if (tid < d) red[tid] = fmaxf(red[tid], red[tid + d]);
        __syncthreads();
    }
    m = red[0];
    __syncthreads();

    float s = 0.f;
    for (int v = tid; v < VSZ; v += 1024) s += expf(row[v] - m);
    red[tid] = s;
    __syncthreads();
    for (int d = 512; d > 0; d >>= 1) {
        if (tid < d) red[tid] += red[tid + d];
        __syncthreads();
    }
    float lse = m + logf(red[0]);
    for (int v = tid; v < VSZ; v += 1024) row[v] -= lse;
}

// ---------------- launch ----------------
extern "C" void kernel_launch(void* const* d_in, const int* in_sizes, int n_in,
                              void* d_out, int out_size) {
    const int* inp = (const int*)d_in[0];
    const float* hidden = (const float*)d_in[1];
    const float* enc = (const float*)d_in[2];
    const float* emb = (const float*)d_in[3];
    const float* W1 = (const float*)d_in[4];
    const float* W2 = (const float*)d_in[5];
    const float* W3 = (const float*)d_in[6];
    const float* b2 = (const float*)d_in[7];
    const float* b3 = (const float*)d_in[8];
    const float* V = (const float*)d_in[9];
    const float* Wih0 = (const float*)d_in[10];
    const float* Whh0 = (const float*)d_in[11];
    const float* bih0 = (const float*)d_in[12];
    const float* bhh0 = (const float*)d_in[13];
    const float* Wih1 = (const float*)d_in[14];
    const float* Whh1 = (const float*)d_in[15];
    const float* bih1 = (const float*)d_in[16];
    const float* bhh1 = (const float*)d_in[17];
    const float* Wout = (const float*)d_in[18];
    const float* bout = (const float*)d_in[19];

    float* out = (float*)d_out;
    float* hid_out = out + (size_t)Bd * VSZ;

    cudaFuncSetAttribute(scores_mma_kernel,
                         cudaFuncAttributeMaxDynamicSharedMemorySize, SC_SMEM);

    prep_w1_kernel<<<Hd, Hd>>>(W1);
    w2h_kernel<<<Bd, 512>>>(hidden, W2, b2);
    scores_mma_kernel<<<(Bd * Sd) / 128, 256, SC_SMEM>>>(enc, V);
    softmax_kernel<<<Bd, 256>>>();
    xa_kernel<<<dim3(16, Bd), 256>>>(enc);
    res_kernel<<<Bd, 512>>>(inp, emb, W3, b3);
    gru_kernel<<<Bd, 768>>>(hidden, Wih0, Whh0, bih0, bhh0, 0, hid_out);
    gru_kernel<<<Bd, 768>>>(hidden, Wih1, Whh1, bih1, bhh1, 1, hid_out);
    transpose_kernel<<<Bd, Hd>>>();
    logits_kernel<<<VSZ / 64, 256>>>(Wout, bout, out);
    logsoftmax_kernel<<<Bd, 1024>>>(out);
}

// round 5
// speedup vs baseline: 3.1897x; 1.0198x over previous
#include <cuda_runtime.h>
#include <cuda_bf16.h>
#include <cstdint>

#define Bd 128
#define Sd 2048
#define Hd 256
#define Ed 256
#define VSZ 32000

// ---------------- scratch (device globals; no allocation) ----------------
__device__ float g_w2h[Bd * Hd];
__device__ float g_scores[Bd * Sd];
__device__ float g_XaP[16 * Bd * Hd];   // split-S partials for Xa
__device__ float g_h1T[Hd * Bd];

// W1 pre-packed: 4 k-chunks; per chunk: hi block then lo block, each
// 256 n-rows x 72 bf16 (64 data + 8 pad -> 144B rows, conflict-free LDS).
#define PAD_E 72
#define CH_HALF_E (Hd * PAD_E)           // 18432 elems = 36864 B
#define CH_E (2 * CH_HALF_E)
__device__ __align__(16) __nv_bfloat16 g_W1p[4 * CH_E];

typedef unsigned long long u64;

// ---------------- helpers ----------------
__device__ __forceinline__ u64 pack2(float x, float y) {
    u64 d;
    asm("mov.b64 %0, {%1, %2};" : "=l"(d)
        : "r"(__float_as_uint(x)), "r"(__float_as_uint(y)));
    return d;
}
__device__ __forceinline__ u64 ffma2(u64 a, u64 b, u64 c) {
    u64 d;
    asm("fma.rn.f32x2 %0, %1, %2, %3;" : "=l"(d) : "l"(a), "l"(b), "l"(c));
    return d;
}
__device__ __forceinline__ float2 unpack2(u64 v) {
    unsigned lo, hi;
    asm("mov.b64 {%0, %1}, %2;" : "=r"(lo), "=r"(hi) : "l"(v));
    float2 r;
    r.x = __uint_as_float(lo);
    r.y = __uint_as_float(hi);
    return r;
}
__device__ __forceinline__ float fast_tanh(float x) {
    float y;
    asm("tanh.approx.f32 %0, %1;" : "=f"(y) : "f"(x));
    return y;
}
__device__ __forceinline__ uint32_t smem_u32(const void* p) {
    uint32_t a;
    asm("{ .reg .u64 t; cvta.to.shared.u64 t, %1; cvt.u32.u64 %0, t; }"
        : "=r"(a) : "l"(p));
    return a;
}
__device__ __forceinline__ void cp16(uint32_t dst, const void* src) {
    asm volatile("cp.async.cg.shared.global [%0], [%1], 16;"
                 :: "r"(dst), "l"(src) : "memory");
}
__device__ __forceinline__ void cp_commit() {
    asm volatile("cp.async.commit_group;" ::: "memory");
}
template <int N>
__device__ __forceinline__ void cp_wait() {
    asm volatile("cp.async.wait_group %0;" :: "n"(N) : "memory");
}
__device__ __forceinline__ void mma_bf16(float* d, const uint32_t* a,
                                         uint32_t b0, uint32_t b1) {
    asm volatile(
        "mma.sync.aligned.m16n8k16.row.col.f32.bf16.bf16.f32 "
        "{%0,%1,%2,%3}, {%4,%5,%6,%7}, {%8,%9}, {%0,%1,%2,%3};"
        : "+f"(d[0]), "+f"(d[1]), "+f"(d[2]), "+f"(d[3])
        : "r"(a[0]), "r"(a[1]), "r"(a[2]), "r"(a[3]), "r"(b0), "r"(b1));
}

// ---------------- P0: pack W1 (transpose + bf16 hi/lo split, padded) -------
__global__ void prep_w1_kernel(const float* __restrict__ W1) {
    int n = blockIdx.x;
    int k = threadIdx.x;
    float x = W1[k * Hd + n];
    __nv_bfloat16 h = __float2bfloat16_rn(x);
    __nv_bfloat16 l = __float2bfloat16_rn(x - __bfloat162float(h));
    int c = k >> 6;
    int kk = k & 63;
    g_W1p[c * CH_E + n * PAD_E + kk] = h;
    g_W1p[c * CH_E + CH_HALF_E + n * PAD_E + kk] = l;
}

// ---------------- K1: w2h = hidden[1] @ W2 + b2 ----------------
__global__ void w2h_kernel(const float* __restrict__ hidden,
                           const float* __restrict__ W2,
                           const float* __restrict__ b2) {
    int b = blockIdx.x;
    int tid = threadIdx.x;  // 512
    int k = tid & 255;
    int h = tid >> 8;
    __shared__ float sh[Hd];
    __shared__ float part[512];
    if (tid < Hd) sh[tid] = hidden[(Bd + b) * Hd + tid];
    __syncthreads();
    float acc = 0.f;
#pragma unroll 16
    for (int j = h * 128; j < h * 128 + 128; j++) acc += sh[j] * W2[j * Hd + k];
    part[tid] = acc;
    __syncthreads();
    if (tid < 256) g_w2h[b * Hd + tid] = part[tid] + part[tid + 256] + b2[tid];
}

// ---------------- K2: scores via mma.sync, 512 threads, cp.async pipeline --
// CTA: 128m x 256n; 16 warps = 4m x 4n; warp tile 32m x 64n.
// SMEM: A hi [128 x 528B] = 67584; A lo +67584; B: 2 x 36864 at 135168.
#define SA_HI 0
#define SA_LO 67584
#define SB_OFF 135168
#define SB_STRIDE 36864
#define SC_SMEM (135168 + 2 * 36864)
__global__ __launch_bounds__(512, 1)
void scores_mma_kernel(const float* __restrict__ enc,
                       const float* __restrict__ Vv) {
    extern __shared__ __align__(16) char smem[];
    const uint32_t sm_b = smem_u32(smem);
    const int tid = threadIdx.x;
    const int wid = tid >> 5;
    const int lane = tid & 31;
    const int g = lane >> 2;
    const int t = lane & 3;
    const int wm = wid >> 2;   // 0..3 (m group of 32)
    const int wn = wid & 3;    // 0..3 (n group of 64)
    const int m0 = blockIdx.x * 128;
    const int b = m0 >> 11;
    const int s0 = m0 & (Sd - 1);

    float acc[2][8][4];
#pragma unroll
    for (int f = 0; f < 2; f++)
#pragma unroll
        for (int j = 0; j < 8; j++)
#pragma unroll
            for (int q = 0; q < 4; q++) acc[f][j][q] = 0.f;

    // ---- issue B stage 0 (chunk 0, hi half: 36864 B = 2304 x 16B) ----
    {
        const char* src = (const char*)g_W1p;
#pragma unroll
        for (int i = 0; i < 5; i++) {
            int idx = tid + i * 512;
            if (idx < 2304) cp16(sm_b + SB_OFF + idx * 16, src + idx * 16);
        }
        cp_commit();
    }

    // ---- fill A (128 x 256 fp32 -> hi/lo bf16), overlaps with cp.async ----
    {
        const float* encb = enc + (size_t)m0 * Hd;
#pragma unroll
        for (int i = 0; i < 32; i++) {
            int idx = tid + i * 512;        // 16384 float2
            int row = idx >> 7;
            int kp = idx & 127;
            float2 v = *(const float2*)(encb + (size_t)row * Hd + kp * 2);
            __nv_bfloat16 h0 = __float2bfloat16_rn(v.x);
            __nv_bfloat16 h1 = __float2bfloat16_rn(v.y);
            __nv_bfloat16 l0 = __float2bfloat16_rn(v.x - __bfloat162float(h0));
            __nv_bfloat16 l1 = __float2bfloat16_rn(v.y - __bfloat162float(h1));
            __nv_bfloat162 hp = {h0, h1};
            __nv_bfloat162 lp = {l0, l1};
            uint32_t off = row * 528 + kp * 4;
            *(uint32_t*)(smem + SA_HI + off) = *(uint32_t*)&hp;
            *(uint32_t*)(smem + SA_LO + off) = *(uint32_t*)&lp;
        }
    }

    // ---- 8 pipelined B stages: (chunk 0..3) x (hi, lo) ----
#pragma unroll
    for (int s = 0; s < 8; s++) {
        if (s < 7) {
            int ns = s + 1;
            int nc = ns >> 1;
            int nh = ns & 1;
            const char* src = (const char*)g_W1p +
                              ((size_t)nc * CH_E + (size_t)nh * CH_HALF_E) * 2;
            uint32_t dst = sm_b + SB_OFF + (ns & 1) * SB_STRIDE;
#pragma unroll
            for (int i = 0; i < 5; i++) {
                int idx = tid + i * 512;
                if (idx < 2304) cp16(dst + idx * 16, src + idx * 16);
            }
            cp_commit();
            cp_wait<1>();
        } else {
            cp_wait<0>();
        }
        __syncthreads();

        const int c = s >> 1;
        const bool hi = (s & 1) == 0;
        const char* Bb = smem + SB_OFF + (s & 1) * SB_STRIDE;

#pragma unroll
        for (int ks = 0; ks < 4; ks++) {
            uint32_t ah[2][4], al[2][4];
#pragma unroll
            for (int f = 0; f < 2; f++) {
                int r0 = wm * 32 + f * 16 + g;
                uint32_t o0 = r0 * 528 + c * 128 + ks * 32 + t * 4;
                uint32_t o1 = o0 + 8 * 528;
                ah[f][0] = *(const uint32_t*)(smem + SA_HI + o0);
                ah[f][1] = *(const uint32_t*)(smem + SA_HI + o1);
                ah[f][2] = *(const uint32_t*)(smem + SA_HI + o0 + 16);
                ah[f][3] = *(const uint32_t*)(smem + SA_HI + o1 + 16);
                if (hi) {
                    al[f][0] = *(const uint32_t*)(smem + SA_LO + o0);
                    al[f][1] = *(const uint32_t*)(smem + SA_LO + o1);
                    al[f][2] = *(const uint32_t*)(smem + SA_LO + o0 + 16);
                    al[f][3] = *(const uint32_t*)(smem + SA_LO + o1 + 16);
                }
            }
#pragma unroll
            for (int j = 0; j < 8; j++) {
                int n = wn * 64 + 8 * j + g;
                uint32_t bo = n * 144 + ks * 32 + t * 4;
                uint32_t b0 = *(const uint32_t*)(Bb + bo);
                uint32_t b1 = *(const uint32_t*)(Bb + bo + 16);
#pragma unroll
                for (int f = 0; f < 2; f++) {
                    mma_bf16(acc[f][j], ah[f], b0, b1);
                    if (hi) mma_bf16(acc[f][j], al[f], b0, b1);
                }
            }
        }
        __syncthreads();
    }

    // ---- epilogue: score[m] = sum_n V[n] * tanh(D[m][n] + w2h[b][n]) ----
    float* sw2 = (float*)smem;                 // 256 f
    float* sV = (float*)(smem + 1024);         // 256 f
    float* sp = (float*)(smem + 2048);         // 4 n-groups x 128 rows
    if (tid < 256) {
        sw2[tid] = g_w2h[b * Hd + tid];
        sV[tid] = Vv[tid];
    }
    __syncthreads();

    float p[2][2] = {{0.f, 0.f}, {0.f, 0.f}};
#pragma unroll
    for (int f = 0; f < 2; f++)
#pragma unroll
        for (int j = 0; j < 8; j++) {
            int cc = wn * 64 + 8 * j + 2 * t;
            float v0 = sV[cc], v1 = sV[cc + 1];
            float w0 = sw2[cc], w1 = sw2[cc + 1];
            p[f][0] += v0 * fast_tanh(acc[f][j][0] + w0)
                     + v1 * fast_tanh(acc[f][j][1] + w1);
            p[f][1] += v0 * fast_tanh(acc[f][j][2] + w0)
                     + v1 * fast_tanh(acc[f][j][3] + w1);
        }
#pragma unroll
    for (int f = 0; f < 2; f++)
#pragma unroll
        for (int u = 0; u < 2; u++) {
            float v = p[f][u];
            v += __shfl_xor_sync(0xffffffffu, v, 1);
            v += __shfl_xor_sync(0xffffffffu, v, 2);
            if (t == 0) {
                int r = wm * 32 + f * 16 + g + 8 * u;
                sp[wn * 128 + r] = v;
            }
        }
    __syncthreads();
    if (tid < 128)
        g_scores[b * Sd + s0 + tid] =
            sp[tid] + sp[128 + tid] + sp[256 + tid] + sp[384 + tid];
}

// ---------------- K3a: softmax over S (in-place -> probabilities) ---------
__global__ void softmax_kernel() {
    const int b = blockIdx.x;
    const int tid = threadIdx.x;  // 256
    __shared__ float sa[Sd];
    __shared__ float red[256];

    float m = -1e30f;
    for (int s = tid; s < Sd; s += 256) {
        float v = g_scores[b * Sd + s];
        sa[s] = v;
        m = fmaxf(m, v);
    }
    red[tid] = m;
    __syncthreads();
    for (int d = 128; d > 0; d >>= 1) {
        if (tid < d) red[tid] = fmaxf(red[tid], red[tid + d]);
        __syncthreads();
    }
    m = red[0];
    __syncthreads();

    float sum = 0.f;
    for (int s = tid; s < Sd; s += 256) {
        float e = expf(sa[s] - m);
        sa[s] = e;
        sum += e;
    }
    red[tid] = sum;
    __syncthreads();
    for (int d = 128; d > 0; d >>= 1) {
        if (tid < d) red[tid] += red[tid + d];
        __syncthreads();
    }
    float inv = 1.f / red[0];
    for (int s = tid; s < Sd; s += 256)
        g_scores[b * Sd + s] = sa[s] * inv;
}

// ---------------- K3b: Xa partials, split over 16 S-chunks ----------------
__global__ void xa_kernel(const float* __restrict__ enc) {
    const int chunk = blockIdx.x;
    const int b = blockIdx.y;
    const int tid = threadIdx.x;  // 256
    __shared__ float a_s[128];
    if (tid < 128) a_s[tid] = g_scores[b * Sd + chunk * 128 + tid];
    __syncthreads();
    const float* eb = enc + ((size_t)b * Sd + chunk * 128) * Hd + tid;
    float acc = 0.f;
#pragma unroll 8
    for (int s = 0; s < 128; s++) acc += a_s[s] * eb[(size_t)s * Hd];
    g_XaP[((size_t)chunk * Bd + b) * Hd + tid] = acc;
}

// ---------------- K4: fused res + GRU0 + GRU1 + transpose -----------------
__global__ __launch_bounds__(768)
void post_kernel(const int* __restrict__ inp,
                 const float* __restrict__ emb,
                 const float* __restrict__ W3,
                 const float* __restrict__ b3,
                 const float* __restrict__ hidden,
                 const float* __restrict__ Wih0,
                 const float* __restrict__ Whh0,
                 const float* __restrict__ bih0,
                 const float* __restrict__ bhh0,
                 const float* __restrict__ Wih1,
                 const float* __restrict__ Whh1,
                 const float* __restrict__ bih1,
                 const float* __restrict__ bhh1,
                 float* __restrict__ hid_out) {
    const int b = blockIdx.x;
    const int tid = threadIdx.x;  // 768
    __shared__ float cat[Ed + Hd];
    __shared__ float part[512];
    __shared__ float sgi[768], sgh[768];
    __shared__ float sx[Hd], sh[Hd];

    // ---- res = [emb[inp]; Xa] @ W3 + b3 ----
    int token = inp[b];
    if (tid < Ed) {
        cat[tid] = emb[(size_t)token * Ed + tid];
    } else if (tid < Ed + Hd) {
        int hh = tid - Ed;
        float x = 0.f;
#pragma unroll
        for (int i = 0; i < 16; i++)
            x += g_XaP[((size_t)i * Bd + b) * Hd + hh];
        cat[tid] = x;
    }
    __syncthreads();
    if (tid < 512) {
        int k = tid & 255;
        int h = tid >> 8;
        float acc = 0.f;
#pragma unroll 16
        for (int j = h * 256; j < h * 256 + 256; j++)
            acc += cat[j] * W3[j * Hd + k];
        part[tid] = acc;
    }
    __syncthreads();
    if (tid < 256) {
        sx[tid] = part[tid] + part[tid + 256] + b3[tid];
        sh[tid] = hidden[b * Hd + tid];  // layer 0 state
    }
    __syncthreads();

    // ---- two GRU cells ----
#pragma unroll
    for (int cell = 0; cell < 2; cell++) {
        const float* Wih = cell ? Wih1 : Wih0;
        const float* Whh = cell ? Whh1 : Whh0;
        const float* bih = cell ? bih1 : bih0;
        const float* bhh = cell ? bhh1 : bhh0;
        {
            int gidx = tid;
            const float4* wi = (const float4*)(Wih + (size_t)gidx * Hd);
            const float4* wh = (const float4*)(Whh + (size_t)gidx * Hd);
            float gi = bih[gidx], gh = bhh[gidx];
#pragma unroll 16
            for (int q = 0; q < Hd / 4; q++) {
                float4 a = wi[q];
                float4 c = wh[q];
                float4 xv = *(const float4*)&sx[q * 4];
                float4 hv = *(const float4*)&sh[q * 4];
                gi += a.x * xv.x + a.y * xv.y + a.z * xv.z + a.w * xv.w;
                gh += c.x * hv.x + c.y * hv.y + c.z * hv.z + c.w * hv.w;
            }
            sgi[gidx] = gi;
            sgh[gidx] = gh;
        }
        __syncthreads();
        if (tid < 256) {
            int j = tid;
            float r = 1.f / (1.f + expf(-(sgi[j] + sgh[j])));
            float z = 1.f / (1.f + expf(-(sgi[Hd + j] + sgh[Hd + j])));
            float n = tanhf(sgi[2 * Hd + j] + r * sgh[2 * Hd + j]);
            float hn = (1.f - z) * n + z * sh[j];
            hid_out[((size_t)cell * Bd + b) * Hd + j] = hn;
            if (cell == 0) {
                part[j] = hn;  // stage h0
            } else {
                g_h1T[j * Bd + b] = hn;
            }
        }
        __syncthreads();
        if (cell == 0 && tid < 256) {
            sx[tid] = part[tid];
            sh[tid] = hidden[(Bd + b) * Hd + tid];  // layer 1 state
        }
        __syncthreads();
    }
}

// ---------------- K7: logits = h1 @ Wout^T + bout ----------------
__global__ __launch_bounds__(256)
void logits_kernel(const float* __restrict__ Wout,
                   const float* __restrict__ bout,
                   float* __restrict__ out) {
    __shared__ float wout_s[64 * 64];
    __shared__ float h1s[64 * 128];
    const int v0 = blockIdx.x * 64;
    const int tid = threadIdx.x;
    const int tx = tid & 15;
    const int ty = tid >> 4;

    u64 acc[4][4];
#pragma unroll
    for (int i = 0; i < 4; i++)
#pragma unroll
        for (int j = 0; j < 4; j++) acc[i][j] = 0ull;

    for (int kk = 0; kk < Hd; kk += 64) {
#pragma unroll
        for (int t = 0; t < 4; t++) {
            int q = tid + t * 256;
            int row = q >> 4;
            int c4 = (q & 15) * 4;
            *(float4*)&wout_s[row * 64 + c4] =
                *(const float4*)(Wout + (size_t)(v0 + row) * Hd + kk + c4);
        }
#pragma unroll
        for (int t = 0; t < 8; t++) {
            int q = tid + t * 256;
            int row = q >> 5;
            int c4 = (q & 31) * 4;
            *(float4*)&h1s[row * 128 + c4] =
                *(const float4*)(g_h1T + (size_t)(kk + row) * Bd + c4);
        }
        __syncthreads();
#pragma unroll 8
        for (int k = 0; k < 64; k++) {
            u64 av[4];
#pragma unroll
            for (int i = 0; i < 4; i++) {
                float a = wout_s[(ty * 4 + i) * 64 + k];
                av[i] = pack2(a, a);
            }
#pragma unroll
            for (int j = 0; j < 4; j++) {
                u64 bv = *(const u64*)&h1s[k * 128 + tx * 2 + j * 32];
#pragma unroll
                for (int i = 0; i < 4; i++) acc[i][j] = ffma2(av[i], bv, acc[i][j]);
            }
        }
        __syncthreads();
    }

#pragma unroll
    for (int i = 0; i < 4; i++)
#pragma unroll
        for (int j = 0; j < 4; j++) {
            float2 a = unpack2(acc[i][j]);
            int v = ty * 4 + i;
            int bb = tx * 2 + j * 32;
            h1s[bb * 64 + v] = a.x;
            h1s[(bb + 1) * 64 + v] = a.y;
        }
    __syncthreads();
    for (int q = tid; q < 8192; q += 256) {
        int bb = q >> 6;
        int v = q & 63;
        out[(size_t)bb * VSZ + v0 + v] = h1s[q] + bout[v0 + v];
    }
}

// ---------------- K8: in-place log_softmax over vocab ----------------
__global__ __launch_bounds__(1024)
void logsoftmax_kernel(float* __restrict__ out) {
    const int b = blockIdx.x;
    const int tid = threadIdx.x;  // 1024
    __shared__ float red[1024];
    float* row = out + (size_t)b * VSZ;

    float m = -1e30f;
    for (int v = tid; v < VSZ; v += 1024) m = fmaxf(m, row[v]);
    red[tid] = m;
    __syncthreads();
    for (int d = 512; d > 0; d >>= 1) {
        if (tid < d) red[tid] = fmaxf(red[tid], red[tid + d]);
        __syncthreads();
    }
    m = red[0];
    __syncthreads();

    float s = 0.f;
    for (int v = tid; v < VSZ; v += 1024) s += expf(row[v] - m);
    red[tid] = s;
    __syncthreads();
    for (int d = 512; d > 0; d >>= 1) {
        if (tid < d) red[tid] += red[tid + d];
        __syncthreads();
    }
    float lse = m + logf(red[0]);
    for (int v = tid; v < VSZ; v += 1024) row[v] -= lse;
}

// ---------------- launch ----------------
extern "C" void kernel_launch(void* const* d_in, const int* in_sizes, int n_in,
                              void* d_out, int out_size) {
    const int* inp = (const int*)d_in[0];
    const float* hidden = (const float*)d_in[1];
    const float* enc = (const float*)d_in[2];
    const float* emb = (const float*)d_in[3];
    const float* W1 = (const float*)d_in[4];
    const float* W2 = (const float*)d_in[5];
    const float* W3 = (const float*)d_in[6];
    const float* b2 = (const float*)d_in[7];
    const float* b3 = (const float*)d_in[8];
    const float* V = (const float*)d_in[9];
    const float* Wih0 = (const float*)d_in[10];
    const float* Whh0 = (const float*)d_in[11];
    const float* bih0 = (const float*)d_in[12];
    const float* bhh0 = (const float*)d_in[13];
    const float* Wih1 = (const float*)d_in[14];
    const float* Whh1 = (const float*)d_in[15];
    const float* bih1 = (const float*)d_in[16];
    const float* bhh1 = (const float*)d_in[17];
    const float* Wout = (const float*)d_in[18];
    const float* bout = (const float*)d_in[19];

    float* out = (float*)d_out;
    float* hid_out = out + (size_t)Bd * VSZ;

    cudaFuncSetAttribute(scores_mma_kernel,
                         cudaFuncAttributeMaxDynamicSharedMemorySize, SC_SMEM);

    prep_w1_kernel<<<Hd, Hd>>>(W1);
    w2h_kernel<<<Bd, 512>>>(hidden, W2, b2);
    scores_mma_kernel<<<(Bd * Sd) / 128, 512, SC_SMEM>>>(enc, V);
    softmax_kernel<<<Bd, 256>>>();
    xa_kernel<<<dim3(16, Bd), 256>>>(enc);
    post_kernel<<<Bd, 768>>>(inp, emb, W3, b3, hidden,
                             Wih0, Whh0, bih0, bhh0,
                             Wih1, Whh1, bih1, bhh1, hid_out);
    logits_kernel<<<VSZ / 64, 256>>>(Wout, bout, out);
    logsoftmax_kernel<<<Bd, 1024>>>(out);
}

// round 6
// speedup vs baseline: 3.7018x; 1.1605x over previous
#include <cuda_runtime.h>
#include <cuda_fp16.h>
#include <cstdint>

#define Bd 128
#define Sd 2048
#define Hd 256
#define Ed 256
#define VSZ 32000

// ---------------- scratch (device globals; no allocation) ----------------
__device__ float g_w2h[Bd * Hd];
__device__ float g_scores[Bd * Sd];
__device__ float g_XaP[16 * Bd * Hd];   // split-S partials for Xa
__device__ float g_h1T[Hd * Bd];

// W1 pre-packed fp16: 4 k-chunks, each 256 n-rows x 72 fp16
// (64 data + 8 pad -> 144B rows, conflict-free fragment LDS).
#define PAD_E 72
#define CH_HALF_E (Hd * PAD_E)           // 18432 elems = 36864 B per chunk
__device__ __align__(16) __half g_W1p[4 * CH_HALF_E];

typedef unsigned long long u64;

// ---------------- helpers ----------------
__device__ __forceinline__ u64 pack2(float x, float y) {
    u64 d;
    asm("mov.b64 %0, {%1, %2};" : "=l"(d)
        : "r"(__float_as_uint(x)), "r"(__float_as_uint(y)));
    return d;
}
__device__ __forceinline__ u64 ffma2(u64 a, u64 b, u64 c) {
    u64 d;
    asm("fma.rn.f32x2 %0, %1, %2, %3;" : "=l"(d) : "l"(a), "l"(b), "l"(c));
    return d;
}
__device__ __forceinline__ float2 unpack2(u64 v) {
    unsigned lo, hi;
    asm("mov.b64 {%0, %1}, %2;" : "=r"(lo), "=r"(hi) : "l"(v));
    float2 r;
    r.x = __uint_as_float(lo);
    r.y = __uint_as_float(hi);
    return r;
}
__device__ __forceinline__ float fast_tanh(float x) {
    float y;
    asm("tanh.approx.f32 %0, %1;" : "=f"(y) : "f"(x));
    return y;
}
__device__ __forceinline__ uint32_t smem_u32(const void* p) {
    uint32_t a;
    asm("{ .reg .u64 t; cvta.to.shared.u64 t, %1; cvt.u32.u64 %0, t; }"
        : "=r"(a) : "l"(p));
    return a;
}
__device__ __forceinline__ void cp16(uint32_t dst, const void* src) {
    asm volatile("cp.async.cg.shared.global [%0], [%1], 16;"
                 :: "r"(dst), "l"(src) : "memory");
}
__device__ __forceinline__ void cp_commit() {
    asm volatile("cp.async.commit_group;" ::: "memory");
}
template <int N>
__device__ __forceinline__ void cp_wait() {
    asm volatile("cp.async.wait_group %0;" :: "n"(N) : "memory");
}
__device__ __forceinline__ void mma_fp16(float* d, const uint32_t* a,
                                         uint32_t b0, uint32_t b1) {
    asm volatile(
        "mma.sync.aligned.m16n8k16.row.col.f32.f16.f16.f32 "
        "{%0,%1,%2,%3}, {%4,%5,%6,%7}, {%8,%9}, {%0,%1,%2,%3};"
        : "+f"(d[0]), "+f"(d[1]), "+f"(d[2]), "+f"(d[3])
        : "r"(a[0]), "r"(a[1]), "r"(a[2]), "r"(a[3]), "r"(b0), "r"(b1));
}

// ---------------- P0: pack W1 (transpose + fp16, padded) ----------------
__global__ void prep_w1_kernel(const float* __restrict__ W1) {
    int n = blockIdx.x;
    int k = threadIdx.x;
    float x = W1[k * Hd + n];
    int c = k >> 6;
    int kk = k & 63;
    g_W1p[c * CH_HALF_E + n * PAD_E + kk] = __float2half_rn(x);
}

// ---------------- K1: w2h = hidden[1] @ W2 + b2 ----------------
__global__ void w2h_kernel(const float* __restrict__ hidden,
                           const float* __restrict__ W2,
                           const float* __restrict__ b2) {
    int b = blockIdx.x;
    int tid = threadIdx.x;  // 512
    int k = tid & 255;
    int h = tid >> 8;
    __shared__ float sh[Hd];
    __shared__ float part[512];
    if (tid < Hd) sh[tid] = hidden[(Bd + b) * Hd + tid];
    __syncthreads();
    float acc = 0.f;
#pragma unroll 16
    for (int j = h * 128; j < h * 128 + 128; j++) acc += sh[j] * W2[j * Hd + k];
    part[tid] = acc;
    __syncthreads();
    if (tid < 256) g_w2h[b * Hd + tid] = part[tid] + part[tid + 256] + b2[tid];
}

// ---------------- K2: scores via fp16 mma.sync, A-split 2-MMA -------------
// CTA: 128m x 256n; 16 warps = 4m x 4n; warp tile 32m x 64n.
// u = enc@W1: A = ah + al (fp16 split of enc), B = fp16(W1).
// SMEM: A hi [128 x 528B] = 67584; A lo +67584; B: 2 x 36864 at 135168.
#define SA_HI 0
#define SA_LO 67584
#define SB_OFF 135168
#define SB_STRIDE 36864
#define SC_SMEM (135168 + 2 * 36864)
__global__ __launch_bounds__(512, 1)
void scores_mma_kernel(const float* __restrict__ enc,
                       const float* __restrict__ Vv) {
    extern __shared__ __align__(16) char smem[];
    const uint32_t sm_b = smem_u32(smem);
    const int tid = threadIdx.x;
    const int wid = tid >> 5;
    const int lane = tid & 31;
    const int g = lane >> 2;
    const int t = lane & 3;
    const int wm = wid >> 2;   // 0..3 (m group of 32)
    const int wn = wid & 3;    // 0..3 (n group of 64)
    const int m0 = blockIdx.x * 128;
    const int b = m0 >> 11;
    const int s0 = m0 & (Sd - 1);

    float acc[2][8][4];
#pragma unroll
    for (int f = 0; f < 2; f++)
#pragma unroll
        for (int j = 0; j < 8; j++)
#pragma unroll
            for (int q = 0; q < 4; q++) acc[f][j][q] = 0.f;

    // ---- issue B stage 0 (chunk 0: 36864 B = 2304 x 16B) ----
    {
        const char* src = (const char*)g_W1p;
#pragma unroll
        for (int i = 0; i < 5; i++) {
            int idx = tid + i * 512;
            if (idx < 2304) cp16(sm_b + SB_OFF + idx * 16, src + idx * 16);
        }
        cp_commit();
    }

    // ---- fill A (128 x 256 fp32 -> fp16 hi/lo), overlaps with cp.async ----
    {
        const float* encb = enc + (size_t)m0 * Hd;
#pragma unroll
        for (int i = 0; i < 32; i++) {
            int idx = tid + i * 512;        // 16384 float2
            int row = idx >> 7;
            int kp = idx & 127;
            float2 v = *(const float2*)(encb + (size_t)row * Hd + kp * 2);
            __half h0 = __float2half_rn(v.x);
            __half h1 = __float2half_rn(v.y);
            __half l0 = __float2half_rn(v.x - __half2float(h0));
            __half l1 = __float2half_rn(v.y - __half2float(h1));
            __half2 hp = {h0, h1};
            __half2 lp = {l0, l1};
            uint32_t off = row * 528 + kp * 4;
            *(uint32_t*)(smem + SA_HI + off) = *(uint32_t*)&hp;
            *(uint32_t*)(smem + SA_LO + off) = *(uint32_t*)&lp;
        }
    }

    // ---- 4 pipelined B stages (one per k-chunk) ----
#pragma unroll
    for (int c = 0; c < 4; c++) {
        if (c < 3) {
            const char* src = (const char*)(g_W1p + (size_t)(c + 1) * CH_HALF_E);
            uint32_t dst = sm_b + SB_OFF + ((c + 1) & 1) * SB_STRIDE;
#pragma unroll
            for (int i = 0; i < 5; i++) {
                int idx = tid + i * 512;
                if (idx < 2304) cp16(dst + idx * 16, src + idx * 16);
            }
            cp_commit();
            cp_wait<1>();
        } else {
            cp_wait<0>();
        }
        __syncthreads();

        const char* Bb = smem + SB_OFF + (c & 1) * SB_STRIDE;

#pragma unroll
        for (int ks = 0; ks < 4; ks++) {
            uint32_t ah[2][4], al[2][4];
#pragma unroll
            for (int f = 0; f < 2; f++) {
                int r0 = wm * 32 + f * 16 + g;
                uint32_t o0 = r0 * 528 + c * 128 + ks * 32 + t * 4;
                uint32_t o1 = o0 + 8 * 528;
                ah[f][0] = *(const uint32_t*)(smem + SA_HI + o0);
                ah[f][1] = *(const uint32_t*)(smem + SA_HI + o1);
                ah[f][2] = *(const uint32_t*)(smem + SA_HI + o0 + 16);
                ah[f][3] = *(const uint32_t*)(smem + SA_HI + o1 + 16);
                al[f][0] = *(const uint32_t*)(smem + SA_LO + o0);
                al[f][1] = *(const uint32_t*)(smem + SA_LO + o1);
                al[f][2] = *(const uint32_t*)(smem + SA_LO + o0 + 16);
                al[f][3] = *(const uint32_t*)(smem + SA_LO + o1 + 16);
            }
#pragma unroll
            for (int j = 0; j < 8; j++) {
                int n = wn * 64 + 8 * j + g;
                uint32_t bo = n * 144 + ks * 32 + t * 4;
                uint32_t b0 = *(const uint32_t*)(Bb + bo);
                uint32_t b1 = *(const uint32_t*)(Bb + bo + 16);
#pragma unroll
                for (int f = 0; f < 2; f++) {
                    mma_fp16(acc[f][j], ah[f], b0, b1);
                    mma_fp16(acc[f][j], al[f], b0, b1);
                }
            }
        }
        __syncthreads();
    }

    // ---- epilogue: score[m] = sum_n V[n] * tanh(D[m][n] + w2h[b][n]) ----
    float* sw2 = (float*)smem;                 // 256 f
    float* sV = (float*)(smem + 1024);         // 256 f
    float* sp = (float*)(smem + 2048);         // 4 n-groups x 128 rows
    if (tid < 256) {
        sw2[tid] = g_w2h[b * Hd + tid];
        sV[tid] = Vv[tid];
    }
    __syncthreads();

    float p[2][2] = {{0.f, 0.f}, {0.f, 0.f}};
#pragma unroll
    for (int f = 0; f < 2; f++)
#pragma unroll
        for (int j = 0; j < 8; j++) {
            int cc = wn * 64 + 8 * j + 2 * t;
            float v0 = sV[cc], v1 = sV[cc + 1];
            float w0 = sw2[cc], w1 = sw2[cc + 1];
            p[f][0] += v0 * fast_tanh(acc[f][j][0] + w0)
                     + v1 * fast_tanh(acc[f][j][1] + w1);
            p[f][1] += v0 * fast_tanh(acc[f][j][2] + w0)
                     + v1 * fast_tanh(acc[f][j][3] + w1);
        }
#pragma unroll
    for (int f = 0; f < 2; f++)
#pragma unroll
        for (int u = 0; u < 2; u++) {
            float v = p[f][u];
            v += __shfl_xor_sync(0xffffffffu, v, 1);
            v += __shfl_xor_sync(0xffffffffu, v, 2);
            if (t == 0) {
                int r = wm * 32 + f * 16 + g + 8 * u;
                sp[wn * 128 + r] = v;
            }
        }
    __syncthreads();
    if (tid < 128)
        g_scores[b * Sd + s0 + tid] =
            sp[tid] + sp[128 + tid] + sp[256 + tid] + sp[384 + tid];
}

// ---------------- K3a: softmax over S (in-place -> probabilities) ---------
__global__ void softmax_kernel() {
    const int b = blockIdx.x;
    const int tid = threadIdx.x;  // 256
    __shared__ float sa[Sd];
    __shared__ float red[256];

    float m = -1e30f;
    for (int s = tid; s < Sd; s += 256) {
        float v = g_scores[b * Sd + s];
        sa[s] = v;
        m = fmaxf(m, v);
    }
    red[tid] = m;
    __syncthreads();
    for (int d = 128; d > 0; d >>= 1) {
        if (tid < d) red[tid] = fmaxf(red[tid], red[tid + d]);
        __syncthreads();
    }
    m = red[0];
    __syncthreads();

    float sum = 0.f;
    for (int s = tid; s < Sd; s += 256) {
        float e = expf(sa[s] - m);
        sa[s] = e;
        sum += e;
    }
    red[tid] = sum;
    __syncthreads();
    for (int d = 128; d > 0; d >>= 1) {
        if (tid < d) red[tid] += red[tid + d];
        __syncthreads();
    }
    float inv = 1.f / red[0];
    for (int s = tid; s < Sd; s += 256)
        g_scores[b * Sd + s] = sa[s] * inv;
}

// ---------------- K3b: Xa partials, split over 16 S-chunks ----------------
__global__ void xa_kernel(const float* __restrict__ enc) {
    const int chunk = blockIdx.x;
    const int b = blockIdx.y;
    const int tid = threadIdx.x;  // 256
    __shared__ float a_s[128];
    if (tid < 128) a_s[tid] = g_scores[b * Sd + chunk * 128 + tid];
    __syncthreads();
    const float* eb = enc + ((size_t)b * Sd + chunk * 128) * Hd + tid;
    float acc = 0.f;
#pragma unroll 8
    for (int s = 0; s < 128; s++) acc += a_s[s] * eb[(size_t)s * Hd];
    g_XaP[((size_t)chunk * Bd + b) * Hd + tid] = acc;
}

// ---------------- K4: fused res + GRU0 + GRU1 + transpose -----------------
__global__ __launch_bounds__(768)
void post_kernel(const int* __restrict__ inp,
                 const float* __restrict__ emb,
                 const float* __restrict__ W3,
                 const float* __restrict__ b3,
                 const float* __restrict__ hidden,
                 const float* __restrict__ Wih0,
                 const float* __restrict__ Whh0,
                 const float* __restrict__ bih0,
                 const float* __restrict__ bhh0,
                 const float* __restrict__ Wih1,
                 const float* __restrict__ Whh1,
                 const float* __restrict__ bih1,
                 const float* __restrict__ bhh1,
                 float* __restrict__ hid_out) {
    const int b = blockIdx.x;
    const int tid = threadIdx.x;  // 768
    __shared__ float cat[Ed + Hd];
    __shared__ float part[512];
    __shared__ float sgi[768], sgh[768];
    __shared__ float sx[Hd], sh[Hd];

    // ---- res = [emb[inp]; Xa] @ W3 + b3 ----
    int token = inp[b];
    if (tid < Ed) {
        cat[tid] = emb[(size_t)token * Ed + tid];
    } else if (tid < Ed + Hd) {
        int hh = tid - Ed;
        float x = 0.f;
#pragma unroll
        for (int i = 0; i < 16; i++)
            x += g_XaP[((size_t)i * Bd + b) * Hd + hh];
        cat[tid] = x;
    }
    __syncthreads();
    if (tid < 512) {
        int k = tid & 255;
        int h = tid >> 8;
        float acc = 0.f;
#pragma unroll 16
        for (int j = h * 256; j < h * 256 + 256; j++)
            acc += cat[j] * W3[j * Hd + k];
        part[tid] = acc;
    }
    __syncthreads();
    if (tid < 256) {
        sx[tid] = part[tid] + part[tid + 256] + b3[tid];
        sh[tid] = hidden[b * Hd + tid];  // layer 0 state
    }
    __syncthreads();

    // ---- two GRU cells ----
#pragma unroll
    for (int cell = 0; cell < 2; cell++) {
        const float* Wih = cell ? Wih1 : Wih0;
        const float* Whh = cell ? Whh1 : Whh0;
        const float* bih = cell ? bih1 : bih0;
        const float* bhh = cell ? bhh1 : bhh0;
        {
            int gidx = tid;
            const float4* wi = (const float4*)(Wih + (size_t)gidx * Hd);
            const float4* wh = (const float4*)(Whh + (size_t)gidx * Hd);
            float gi = bih[gidx], gh = bhh[gidx];
#pragma unroll 16
            for (int q = 0; q < Hd / 4; q++) {
                float4 a = wi[q];
                float4 c = wh[q];
                float4 xv = *(const float4*)&sx[q * 4];
                float4 hv = *(const float4*)&sh[q * 4];
                gi += a.x * xv.x + a.y * xv.y + a.z * xv.z + a.w * xv.w;
                gh += c.x * hv.x + c.y * hv.y + c.z * hv.z + c.w * hv.w;
            }
            sgi[gidx] = gi;
            sgh[gidx] = gh;
        }
        __syncthreads();
        if (tid < 256) {
            int j = tid;
            float r = 1.f / (1.f + expf(-(sgi[j] + sgh[j])));
            float z = 1.f / (1.f + expf(-(sgi[Hd + j] + sgh[Hd + j])));
            float n = tanhf(sgi[2 * Hd + j] + r * sgh[2 * Hd + j]);
            float hn = (1.f - z) * n + z * sh[j];
            hid_out[((size_t)cell * Bd + b) * Hd + j] = hn;
            if (cell == 0) {
                part[j] = hn;  // stage h0
            } else {
                g_h1T[j * Bd + b] = hn;
            }
        }
        __syncthreads();
        if (cell == 0 && tid < 256) {
            sx[tid] = part[tid];
            sh[tid] = hidden[(Bd + b) * Hd + tid];  // layer 1 state
        }
        __syncthreads();
    }
}

// ---------------- K7: logits = h1 @ Wout^T + bout ----------------
__global__ __launch_bounds__(256)
void logits_kernel(const float* __restrict__ Wout,
                   const float* __restrict__ bout,
                   float* __restrict__ out) {
    __shared__ float wout_s[64 * 64];
    __shared__ float h1s[64 * 128];
    const int v0 = blockIdx.x * 64;
    const int tid = threadIdx.x;
    const int tx = tid & 15;
    const int ty = tid >> 4;

    u64 acc[4][4];
#pragma unroll
    for (int i = 0; i < 4; i++)
#pragma unroll
        for (int j = 0; j < 4; j++) acc[i][j] = 0ull;

    for (int kk = 0; kk < Hd; kk += 64) {
#pragma unroll
        for (int t = 0; t < 4; t++) {
            int q = tid + t * 256;
            int row = q >> 4;
            int c4 = (q & 15) * 4;
            *(float4*)&wout_s[row * 64 + c4] =
                *(const float4*)(Wout + (size_t)(v0 + row) * Hd + kk + c4);
        }
#pragma unroll
        for (int t = 0; t < 8; t++) {
            int q = tid + t * 256;
            int row = q >> 5;
            int c4 = (q & 31) * 4;
            *(float4*)&h1s[row * 128 + c4] =
                *(const float4*)(g_h1T + (size_t)(kk + row) * Bd + c4);
        }
        __syncthreads();
#pragma unroll 8
        for (int k = 0; k < 64; k++) {
            u64 av[4];
#pragma unroll
            for (int i = 0; i < 4; i++) {
                float a = wout_s[(ty * 4 + i) * 64 + k];
                av[i] = pack2(a, a);
            }
#pragma unroll
            for (int j = 0; j < 4; j++) {
                u64 bv = *(const u64*)&h1s[k * 128 + tx * 2 + j * 32];
#pragma unroll
                for (int i = 0; i < 4; i++) acc[i][j] = ffma2(av[i], bv, acc[i][j]);
            }
        }
        __syncthreads();
    }

#pragma unroll
    for (int i = 0; i < 4; i++)
#pragma unroll
        for (int j = 0; j < 4; j++) {
            float2 a = unpack2(acc[i][j]);
            int v = ty * 4 + i;
            int bb = tx * 2 + j * 32;
            h1s[bb * 64 + v] = a.x;
            h1s[(bb + 1) * 64 + v] = a.y;
        }
    __syncthreads();
    for (int q = tid; q < 8192; q += 256) {
        int bb = q >> 6;
        int v = q & 63;
        out[(size_t)bb * VSZ + v0 + v] = h1s[q] + bout[v0 + v];
    }
}

// ---------------- K8: in-place log_softmax over vocab ----------------
__global__ __launch_bounds__(1024)
void logsoftmax_kernel(float* __restrict__ out) {
    const int b = blockIdx.x;
    const int tid = threadIdx.x;  // 1024
    __shared__ float red[1024];
    float* row = out + (size_t)b * VSZ;

    float m = -1e30f;
    for (int v = tid; v < VSZ; v += 1024) m = fmaxf(m, row[v]);
    red[tid] = m;
    __syncthreads();
    for (int d = 512; d > 0; d >>= 1) {
        if (tid < d) red[tid] = fmaxf(red[tid], red[tid + d]);
        __syncthreads();
    }
    m = red[0];
    __syncthreads();

    float s = 0.f;
    for (int v = tid; v < VSZ; v += 1024) s += expf(row[v] - m);
    red[tid] = s;
    __syncthreads();
    for (int d = 512; d > 0; d >>= 1) {
        if (tid < d) red[tid] += red[tid + d];
        __syncthreads();
    }
    float lse = m + logf(red[0]);
    for (int v = tid; v < VSZ; v += 1024) row[v] -= lse;
}

// ---------------- launch ----------------
extern "C" void kernel_launch(void* const* d_in, const int* in_sizes, int n_in,
                              void* d_out, int out_size) {
    const int* inp = (const int*)d_in[0];
    const float* hidden = (const float*)d_in[1];
    const float* enc = (const float*)d_in[2];
    const float* emb = (const float*)d_in[3];
    const float* W1 = (const float*)d_in[4];
    const float* W2 = (const float*)d_in[5];
    const float* W3 = (const float*)d_in[6];
    const float* b2 = (const float*)d_in[7];
    const float* b3 = (const float*)d_in[8];
    const float* V = (const float*)d_in[9];
    const float* Wih0 = (const float*)d_in[10];
    const float* Whh0 = (const float*)d_in[11];
    const float* bih0 = (const float*)d_in[12];
    const float* bhh0 = (const float*)d_in[13];
    const float* Wih1 = (const float*)d_in[14];
    const float* Whh1 = (const float*)d_in[15];
    const float* bih1 = (const float*)d_in[16];
    const float* bhh1 = (const float*)d_in[17];
    const float* Wout = (const float*)d_in[18];
    const float* bout = (const float*)d_in[19];

    float* out = (float*)d_out;
    float* hid_out = out + (size_t)Bd * VSZ;

    cudaFuncSetAttribute(scores_mma_kernel,
                         cudaFuncAttributeMaxDynamicSharedMemorySize, SC_SMEM);

    prep_w1_kernel<<<Hd, Hd>>>(W1);
    w2h_kernel<<<Bd, 512>>>(hidden, W2, b2);
    scores_mma_kernel<<<(Bd * Sd) / 128, 512, SC_SMEM>>>(enc, V);
    softmax_kernel<<<Bd, 256>>>();
    xa_kernel<<<dim3(16, Bd), 256>>>(enc);
    post_kernel<<<Bd, 768>>>(inp, emb, W3, b3, hidden,
                             Wih0, Whh0, bih0, bhh0,
                             Wih1, Whh1, bih1, bhh1, hid_out);
    logits_kernel<<<VSZ / 64, 256>>>(Wout, bout, out);
    logsoftmax_kernel<<<Bd, 1024>>>(out);
}

// round 7
// speedup vs baseline: 5.2191x; 1.4099x over previous
#include <cuda_runtime.h>
#include <cuda_fp16.h>
#include <cstdint>

#define Bd 128
#define Sd 2048
#define Hd 256
#define Ed 256
#define VSZ 32000

// ---------------- scratch (device globals; no allocation) ----------------
__device__ float g_w2h[Bd * Hd];
__device__ float g_mz[2 * 2048];           // per (b,chunk) tile: local max, local sum
__device__ float g_XaP[16 * Bd * Hd];      // per-tile partial numerators
__device__ __align__(16) __half g_h1h[Bd * Hd];

// W1 pre-packed fp16: 4 k-chunks, each 256 n-rows x 72 fp16 (144B rows).
#define PAD_E 72
#define CH_HALF_E (Hd * PAD_E)             // 18432 elems = 36864 B per chunk
__device__ __align__(16) __half g_W1p[4 * CH_HALF_E];
// Wout pre-packed fp16: 4 k-chunks x 32000 v-rows x 72 fp16
__device__ __align__(16) __half g_Woutp[4 * VSZ * PAD_E];

// ---------------- helpers ----------------
__device__ __forceinline__ float fast_tanh(float x) {
    float y;
    asm("tanh.approx.f32 %0, %1;" : "=f"(y) : "f"(x));
    return y;
}
__device__ __forceinline__ uint32_t smem_u32(const void* p) {
    uint32_t a;
    asm("{ .reg .u64 t; cvta.to.shared.u64 t, %1; cvt.u32.u64 %0, t; }"
        : "=r"(a) : "l"(p));
    return a;
}
__device__ __forceinline__ void cp16(uint32_t dst, const void* src) {
    asm volatile("cp.async.cg.shared.global [%0], [%1], 16;"
                 :: "r"(dst), "l"(src) : "memory");
}
__device__ __forceinline__ void cp_commit() {
    asm volatile("cp.async.commit_group;" ::: "memory");
}
template <int N>
__device__ __forceinline__ void cp_wait() {
    asm volatile("cp.async.wait_group %0;" :: "n"(N) : "memory");
}
__device__ __forceinline__ void mma_fp16(float* d, const uint32_t* a,
                                         uint32_t b0, uint32_t b1) {
    asm volatile(
        "mma.sync.aligned.m16n8k16.row.col.f32.f16.f16.f32 "
        "{%0,%1,%2,%3}, {%4,%5,%6,%7}, {%8,%9}, {%0,%1,%2,%3};"
        : "+f"(d[0]), "+f"(d[1]), "+f"(d[2]), "+f"(d[3])
        : "r"(a[0]), "r"(a[1]), "r"(a[2]), "r"(a[3]), "r"(b0), "r"(b1));
}

// ---------------- P0: pack W1 (transpose + fp16, padded) ----------------
__global__ void prep_w1_kernel(const float* __restrict__ W1) {
    int n = blockIdx.x;
    int k = threadIdx.x;
    float x = W1[k * Hd + n];
    int c = k >> 6;
    int kk = k & 63;
    g_W1p[c * CH_HALF_E + n * PAD_E + kk] = __float2half_rn(x);
}

// ---------------- P1: pack Wout -> fp16, chunked + padded ----------------
__global__ void prep_wout_kernel(const float* __restrict__ Wout) {
    int idx4 = (blockIdx.x * 256 + threadIdx.x) * 4;  // 8.192M elems
    int v = idx4 >> 8;
    int k = idx4 & 255;
    float4 x = *(const float4*)(Wout + (size_t)v * Hd + k);
    __half2 a = {__float2half_rn(x.x), __float2half_rn(x.y)};
    __half2 b = {__float2half_rn(x.z), __float2half_rn(x.w)};
    uint2 w;
    w.x = *(uint32_t*)&a;
    w.y = *(uint32_t*)&b;
    *(uint2*)&g_Woutp[(size_t)(k >> 6) * VSZ * PAD_E + (size_t)v * PAD_E + (k & 63)] = w;
}

// ---------------- K1: w2h = hidden[1] @ W2 + b2 ----------------
__global__ void w2h_kernel(const float* __restrict__ hidden,
                           const float* __restrict__ W2,
                           const float* __restrict__ b2) {
    int b = blockIdx.x;
    int tid = threadIdx.x;  // 512
    int k = tid & 255;
    int h = tid >> 8;
    __shared__ float sh[Hd];
    __shared__ float part[512];
    if (tid < Hd) sh[tid] = hidden[(Bd + b) * Hd + tid];
    __syncthreads();
    float acc = 0.f;
#pragma unroll 16
    for (int j = h * 128; j < h * 128 + 128; j++) acc += sh[j] * W2[j * Hd + k];
    part[tid] = acc;
    __syncthreads();
    if (tid < 256) g_w2h[b * Hd + tid] = part[tid] + part[tid + 256] + b2[tid];
}

// ---------------- K2: scores + local softmax + partial Xa numerator -------
// CTA: 128m x 256n, 16 warps (4m x 4n), single fp16 mma, 4 cp.async B stages.
// SMEM: A [128 x 528B] = 67584; B: 2 x 36864 at 67584. Epilogue scratch in B0.
#define SA_HI 0
#define SB_OFF 67584
#define SB_STRIDE 36864
#define SC_SMEM (67584 + 2 * 36864)
__global__ __launch_bounds__(512, 1)
void scores_mma_kernel(const float* __restrict__ enc,
                       const float* __restrict__ Vv) {
    extern __shared__ __align__(16) char smem[];
    const uint32_t sm_b = smem_u32(smem);
    const int tid = threadIdx.x;
    const int wid = tid >> 5;
    const int lane = tid & 31;
    const int g = lane >> 2;
    const int t = lane & 3;
    const int wm = wid >> 2;
    const int wn = wid & 3;
    const int b = blockIdx.x >> 4;
    const int chunk = blockIdx.x & 15;
    const int m0 = blockIdx.x * 128;

    float acc[2][8][4];
#pragma unroll
    for (int f = 0; f < 2; f++)
#pragma unroll
        for (int j = 0; j < 8; j++)
#pragma unroll
            for (int q = 0; q < 4; q++) acc[f][j][q] = 0.f;

    // ---- issue B stage 0 ----
    {
        const char* src = (const char*)g_W1p;
#pragma unroll
        for (int i = 0; i < 5; i++) {
            int idx = tid + i * 512;
            if (idx < 2304) cp16(sm_b + SB_OFF + idx * 16, src + idx * 16);
        }
        cp_commit();
    }

    // ---- fill A (128 x 256 fp32 -> fp16), overlaps with cp.async ----
    {
        const float* encb = enc + (size_t)m0 * Hd;
#pragma unroll
        for (int i = 0; i < 32; i++) {
            int idx = tid + i * 512;        // 16384 float2
            int row = idx >> 7;
            int kp = idx & 127;
            float2 v = *(const float2*)(encb + (size_t)row * Hd + kp * 2);
            __half2 hp = {__float2half_rn(v.x), __float2half_rn(v.y)};
            *(uint32_t*)(smem + SA_HI + row * 528 + kp * 4) = *(uint32_t*)&hp;
        }
    }

    // ---- 4 pipelined B stages ----
#pragma unroll
    for (int c = 0; c < 4; c++) {
        if (c < 3) {
            const char* src = (const char*)(g_W1p + (size_t)(c + 1) * CH_HALF_E);
            uint32_t dst = sm_b + SB_OFF + ((c + 1) & 1) * SB_STRIDE;
#pragma unroll
            for (int i = 0; i < 5; i++) {
                int idx = tid + i * 512;
                if (idx < 2304) cp16(dst + idx * 16, src + idx * 16);
            }
            cp_commit();
            cp_wait<1>();
        } else {
            cp_wait<0>();
        }
        __syncthreads();

        const char* Bb = smem + SB_OFF + (c & 1) * SB_STRIDE;
#pragma unroll
        for (int ks = 0; ks < 4; ks++) {
            uint32_t ah[2][4];
#pragma unroll
            for (int f = 0; f < 2; f++) {
                int r0 = wm * 32 + f * 16 + g;
                uint32_t o0 = r0 * 528 + c * 128 + ks * 32 + t * 4;
                uint32_t o1 = o0 + 8 * 528;
                ah[f][0] = *(const uint32_t*)(smem + SA_HI + o0);
                ah[f][1] = *(const uint32_t*)(smem + SA_HI + o1);
                ah[f][2] = *(const uint32_t*)(smem + SA_HI + o0 + 16);
                ah[f][3] = *(const uint32_t*)(smem + SA_HI + o1 + 16);
            }
#pragma unroll
            for (int j = 0; j < 8; j++) {
                int n = wn * 64 + 8 * j + g;
                uint32_t bo = n * 144 + ks * 32 + t * 4;
                uint32_t b0 = *(const uint32_t*)(Bb + bo);
                uint32_t b1 = *(const uint32_t*)(Bb + bo + 16);
#pragma unroll
                for (int f = 0; f < 2; f++) mma_fp16(acc[f][j], ah[f], b0, b1);
            }
        }
        __syncthreads();
    }

    // ---- epilogue: scores -> local softmax -> partial numerator ----
    float* EP = (float*)(smem + SB_OFF);   // B buffer 0 region, dead now
    float* sw2 = EP;                        // 256
    float* sV = EP + 256;                   // 256
    float* sp = EP + 512;                   // 512 (4 n-groups x 128 rows)
    float* red = EP + 1024;                 // 128
    float* e_arr = EP + 1152;               // 128
    float* pN = EP + 1280;                  // 512
    if (tid < 256) {
        sw2[tid] = g_w2h[b * Hd + tid];
        sV[tid] = Vv[tid];
    }
    __syncthreads();

    float p[2][2] = {{0.f, 0.f}, {0.f, 0.f}};
#pragma unroll
    for (int f = 0; f < 2; f++)
#pragma unroll
        for (int j = 0; j < 8; j++) {
            int cc = wn * 64 + 8 * j + 2 * t;
            float v0 = sV[cc], v1 = sV[cc + 1];
            float w0 = sw2[cc], w1 = sw2[cc + 1];
            p[f][0] += v0 * fast_tanh(acc[f][j][0] + w0)
                     + v1 * fast_tanh(acc[f][j][1] + w1);
            p[f][1] += v0 * fast_tanh(acc[f][j][2] + w0)
                     + v1 * fast_tanh(acc[f][j][3] + w1);
        }
#pragma unroll
    for (int f = 0; f < 2; f++)
#pragma unroll
        for (int u = 0; u < 2; u++) {
            float v = p[f][u];
            v += __shfl_xor_sync(0xffffffffu, v, 1);
            v += __shfl_xor_sync(0xffffffffu, v, 2);
            if (t == 0) {
                int r = wm * 32 + f * 16 + g + 8 * u;
                sp[wn * 128 + r] = v;
            }
        }
    __syncthreads();

    float sc = 0.f;
    if (tid < 128) {
        sc = sp[tid] + sp[128 + tid] + sp[256 + tid] + sp[384 + tid];
        red[tid] = sc;
    }
    __syncthreads();
    for (int d = 64; d > 0; d >>= 1) {
        if (tid < d) red[tid] = fmaxf(red[tid], red[tid + d]);
        __syncthreads();
    }
    float mloc = red[0];
    __syncthreads();
    if (tid < 128) {
        float e = expf(sc - mloc);
        e_arr[tid] = e;
        red[tid] = e;
    }
    __syncthreads();
    for (int d = 64; d > 0; d >>= 1) {
        if (tid < d) red[tid] += red[tid + d];
        __syncthreads();
    }
    if (tid == 0) {
        g_mz[2 * blockIdx.x] = mloc;
        g_mz[2 * blockIdx.x + 1] = red[0];
    }

    // partial numerator: N[h] = sum_s e_s * enc[s][h] (fp16 enc from smem)
    int half_id = tid >> 8;
    int h = tid & 255;
    float a2 = 0.f;
#pragma unroll 8
    for (int s = half_id * 64; s < half_id * 64 + 64; s++) {
        __half hv = *(const __half*)(smem + SA_HI + s * 528 + h * 2);
        a2 += e_arr[s] * __half2float(hv);
    }
    pN[half_id * 256 + h] = a2;
    __syncthreads();
    if (tid < 256)
        g_XaP[((size_t)chunk * Bd + b) * Hd + tid] = pN[tid] + pN[256 + tid];
}

// ---------------- K4: fused Xa-combine + res + GRU0 + GRU1 + h1->fp16 ----
__global__ __launch_bounds__(768)
void post_kernel(const int* __restrict__ inp,
                 const float* __restrict__ emb,
                 const float* __restrict__ W3,
                 const float* __restrict__ b3,
                 const float* __restrict__ hidden,
                 const float* __restrict__ Wih0,
                 const float* __restrict__ Whh0,
                 const float* __restrict__ bih0,
                 const float* __restrict__ bhh0,
                 const float* __restrict__ Wih1,
                 const float* __restrict__ Whh1,
                 const float* __restrict__ bih1,
                 const float* __restrict__ bhh1,
                 float* __restrict__ hid_out) {
    const int b = blockIdx.x;
    const int tid = threadIdx.x;  // 768
    __shared__ float cat[Ed + Hd];
    __shared__ float part[512];
    __shared__ float sgi[768], sgh[768];
    __shared__ float sx[Hd], sh[Hd];

    int token = inp[b];
    if (tid < Ed) {
        cat[tid] = emb[(size_t)token * Ed + tid];
    } else if (tid < Ed + Hd) {
        int hh = tid - Ed;
        float mv[16];
        float M = -1e30f;
#pragma unroll
        for (int i = 0; i < 16; i++) {
            mv[i] = g_mz[2 * (b * 16 + i)];
            M = fmaxf(M, mv[i]);
        }
        float Z = 0.f, X = 0.f;
#pragma unroll
        for (int i = 0; i < 16; i++) {
            float w = expf(mv[i] - M);
            Z += w * g_mz[2 * (b * 16 + i) + 1];
            X += w * g_XaP[((size_t)i * Bd + b) * Hd + hh];
        }
        cat[tid] = X / Z;
    }
    __syncthreads();
    if (tid < 512) {
        int k = tid & 255;
        int h = tid >> 8;
        float acc = 0.f;
#pragma unroll 16
        for (int j = h * 256; j < h * 256 + 256; j++)
            acc += cat[j] * W3[j * Hd + k];
        part[tid] = acc;
    }
    __syncthreads();
    if (tid < 256) {
        sx[tid] = part[tid] + part[tid + 256] + b3[tid];
        sh[tid] = hidden[b * Hd + tid];
    }
    __syncthreads();

#pragma unroll
    for (int cell = 0; cell < 2; cell++) {
        const float* Wih = cell ? Wih1 : Wih0;
        const float* Whh = cell ? Whh1 : Whh0;
        const float* bih = cell ? bih1 : bih0;
        const float* bhh = cell ? bhh1 : bhh0;
        {
            int gidx = tid;
            const float4* wi = (const float4*)(Wih + (size_t)gidx * Hd);
            const float4* wh = (const float4*)(Whh + (size_t)gidx * Hd);
            float gi = bih[gidx], gh = bhh[gidx];
#pragma unroll 16
            for (int q = 0; q < Hd / 4; q++) {
                float4 a = wi[q];
                float4 c = wh[q];
                float4 xv = *(const float4*)&sx[q * 4];
                float4 hv = *(const float4*)&sh[q * 4];
                gi += a.x * xv.x + a.y * xv.y + a.z * xv.z + a.w * xv.w;
                gh += c.x * hv.x + c.y * hv.y + c.z * hv.z + c.w * hv.w;
            }
            sgi[gidx] = gi;
            sgh[gidx] = gh;
        }
        __syncthreads();
        if (tid < 256) {
            int j = tid;
            float r = 1.f / (1.f + expf(-(sgi[j] + sgh[j])));
            float z = 1.f / (1.f + expf(-(sgi[Hd + j] + sgh[Hd + j])));
            float n = tanhf(sgi[2 * Hd + j] + r * sgh[2 * Hd + j]);
            float hn = (1.f - z) * n + z * sh[j];
            hid_out[((size_t)cell * Bd + b) * Hd + j] = hn;
            if (cell == 0) {
                part[j] = hn;
            } else {
                g_h1h[b * Hd + j] = __float2half_rn(hn);
            }
        }
        __syncthreads();
        if (cell == 0 && tid < 256) {
            sx[tid] = part[tid];
            sh[tid] = hidden[(Bd + b) * Hd + tid];
        }
        __syncthreads();
    }
}

// ---------------- K7: logits via fp16 mma: out = h1 @ Wout^T + bout -------
// CTA: 128b x 256v, K=256; same structure as scores (single fp16 mma).
#define LG_SMEM (67584 + 2 * 36864)
__global__ __launch_bounds__(512, 1)
void logits_mma_kernel(const float* __restrict__ bout,
                       float* __restrict__ out) {
    extern __shared__ __align__(16) char smem[];
    const uint32_t sm_b = smem_u32(smem);
    const int tid = threadIdx.x;
    const int wid = tid >> 5;
    const int lane = tid & 31;
    const int g = lane >> 2;
    const int t = lane & 3;
    const int wm = wid >> 2;
    const int wn = wid & 3;
    const int v0 = blockIdx.x * 256;

    float acc[2][8][4];
#pragma unroll
    for (int f = 0; f < 2; f++)
#pragma unroll
        for (int j = 0; j < 8; j++)
#pragma unroll
            for (int q = 0; q < 4; q++) acc[f][j][q] = 0.f;

    // B stage 0
    {
        const char* src = (const char*)(g_Woutp + (size_t)v0 * PAD_E);
#pragma unroll
        for (int i = 0; i < 5; i++) {
            int idx = tid + i * 512;
            if (idx < 2304) cp16(sm_b + SB_OFF + idx * 16, src + idx * 16);
        }
        cp_commit();
    }
    // A fill: g_h1h [128 x 256] half -> padded rows
    {
        const uint32_t* src = (const uint32_t*)g_h1h;
#pragma unroll
        for (int i = 0; i < 32; i++) {
            int idx = tid + i * 512;        // 16384 u32
            int row = idx >> 7;
            int c32 = idx & 127;
            *(uint32_t*)(smem + row * 528 + c32 * 4) = src[idx];
        }
    }

#pragma unroll
    for (int c = 0; c < 4; c++) {
        if (c < 3) {
            const char* src =
                (const char*)(g_Woutp + ((size_t)(c + 1) * VSZ + v0) * PAD_E);
            uint32_t dst = sm_b + SB_OFF + ((c + 1) & 1) * SB_STRIDE;
#pragma unroll
            for (int i = 0; i < 5; i++) {
                int idx = tid + i * 512;
                if (idx < 2304) cp16(dst + idx * 16, src + idx * 16);
            }
            cp_commit();
            cp_wait<1>();
        } else {
            cp_wait<0>();
        }
        __syncthreads();

        const char* Bb = smem + SB_OFF + (c & 1) * SB_STRIDE;
#pragma unroll
        for (int ks = 0; ks < 4; ks++) {
            uint32_t ah[2][4];
#pragma unroll
            for (int f = 0; f < 2; f++) {
                int r0 = wm * 32 + f * 16 + g;
                uint32_t o0 = r0 * 528 + c * 128 + ks * 32 + t * 4;
                uint32_t o1 = o0 + 8 * 528;
                ah[f][0] = *(const uint32_t*)(smem + o0);
                ah[f][1] = *(const uint32_t*)(smem + o1);
                ah[f][2] = *(const uint32_t*)(smem + o0 + 16);
                ah[f][3] = *(const uint32_t*)(smem + o1 + 16);
            }
#pragma unroll
            for (int j = 0; j < 8; j++) {
                int n = wn * 64 + 8 * j + g;
                uint32_t bo = n * 144 + ks * 32 + t * 4;
                uint32_t b0 = *(const uint32_t*)(Bb + bo);
                uint32_t b1 = *(const uint32_t*)(Bb + bo + 16);
#pragma unroll
                for (int f = 0; f < 2; f++) mma_fp16(acc[f][j], ah[f], b0, b1);
            }
        }
        __syncthreads();
    }

    // epilogue: stage 64-col groups, add bout, coalesced store
    float* stage = (float*)(smem + SB_OFF);   // 128 x 65 f32 = 33280 B
#pragma unroll
    for (int cg = 0; cg < 4; cg++) {
        if (wn == cg) {
#pragma unroll
            for (int f = 0; f < 2; f++)
#pragma unroll
                for (int j = 0; j < 8; j++)
#pragma unroll
                    for (int q = 0; q < 4; q++) {
                        int row = wm * 32 + f * 16 + g + 8 * (q >> 1);
                        int col = 8 * j + 2 * t + (q & 1);
                        stage[row * 65 + col] = acc[f][j][q];
                    }
        }
        __syncthreads();
#pragma unroll
        for (int i = 0; i < 16; i++) {
            int idx = tid + i * 512;        // 8192
            int row = idx >> 6;
            int col = idx & 63;
            out[(size_t)row * VSZ + v0 + cg * 64 + col] =
                stage[row * 65 + col] + bout[v0 + cg * 64 + col];
        }
        __syncthreads();
    }
}

// ---------------- K8: in-place log_softmax over vocab ----------------
__global__ __launch_bounds__(1024)
void logsoftmax_kernel(float* __restrict__ out) {
    const int b = blockIdx.x;
    const int tid = threadIdx.x;  // 1024
    __shared__ float red[1024];
    float* row = out + (size_t)b * VSZ;

    float m = -1e30f;
    for (int v = tid; v < VSZ; v += 1024) m = fmaxf(m, row[v]);
    red[tid] = m;
    __syncthreads();
    for (int d = 512; d > 0; d >>= 1) {
        if (tid < d) red[tid] = fmaxf(red[tid], red[tid + d]);
        __syncthreads();
    }
    m = red[0];
    __syncthreads();

    float s = 0.f;
    for (int v = tid; v < VSZ; v += 1024) s += expf(row[v] - m);
    red[tid] = s;
    __syncthreads();
    for (int d = 512; d > 0; d >>= 1) {
        if (tid < d) red[tid] += red[tid + d];
        __syncthreads();
    }
    float lse = m + logf(red[0]);
    for (int v = tid; v < VSZ; v += 1024) row[v] -= lse;
}

// ---------------- launch ----------------
extern "C" void kernel_launch(void* const* d_in, const int* in_sizes, int n_in,
                              void* d_out, int out_size) {
    const int* inp = (const int*)d_in[0];
    const float* hidden = (const float*)d_in[1];
    const float* enc = (const float*)d_in[2];
    const float* emb = (const float*)d_in[3];
    const float* W1 = (const float*)d_in[4];
    const float* W2 = (const float*)d_in[5];
    const float* W3 = (const float*)d_in[6];
    const float* b2 = (const float*)d_in[7];
    const float* b3 = (const float*)d_in[8];
    const float* V = (const float*)d_in[9];
    const float* Wih0 = (const float*)d_in[10];
    const float* Whh0 = (const float*)d_in[11];
    const float* bih0 = (const float*)d_in[12];
    const float* bhh0 = (const float*)d_in[13];
    const float* Wih1 = (const float*)d_in[14];
    const float* Whh1 = (const float*)d_in[15];
    const float* bih1 = (const float*)d_in[16];
    const float* bhh1 = (const float*)d_in[17];
    const float* Wout = (const float*)d_in[18];
    const float* bout = (const float*)d_in[19];

    float* out = (float*)d_out;
    float* hid_out = out + (size_t)Bd * VSZ;

    cudaFuncSetAttribute(scores_mma_kernel,
                         cudaFuncAttributeMaxDynamicSharedMemorySize, SC_SMEM);
    cudaFuncSetAttribute(logits_mma_kernel,
                         cudaFuncAttributeMaxDynamicSharedMemorySize, LG_SMEM);

    prep_w1_kernel<<<Hd, Hd>>>(W1);
    prep_wout_kernel<<<8000, 256>>>(Wout);
    w2h_kernel<<<Bd, 512>>>(hidden, W2, b2);
    scores_mma_kernel<<<Bd * 16, 512, SC_SMEM>>>(enc, V);
    post_kernel<<<Bd, 768>>>(inp, emb, W3, b3, hidden,
                             Wih0, Whh0, bih0, bhh0,
                             Wih1, Whh1, bih1, bhh1, hid_out);
    logits_mma_kernel<<<VSZ / 256, 512, LG_SMEM>>>(bout, out);
    logsoftmax_kernel<<<Bd, 1024>>>(out);
}